// round 12
// baseline (speedup 1.0000x reference)
#include <cuda_runtime.h>
#include <cuda_bf16.h>
#include <math.h>
#include <stdint.h>

#define NB   4
#define LSEQ 4096
#define EDIM 1024
#define HDIM 1024
#define ML   (NB * LSEQ)      // 16384

#define QSCALE    16.0f
#define QSCALE_I2 (1.0f / 256.0f)   // 1/(16*16)

// ---------------- scratch (static device arrays; no allocation APIs) -------
__device__ __nv_bfloat16 g_Xhi[ML * EDIM];          // 32 MB
__device__ __nv_bfloat16 g_Xlo[ML * EDIM];
__device__ __align__(128) uint8_t g_X8[ML * EDIM];  // 16 MB s8 (aligned for cp.async)
__device__ __align__(128) uint8_t g_Qk8[ML * EDIM]; // 16 MB s8
__device__ __nv_bfloat16 g_Wvhi[HDIM * EDIM];
__device__ __nv_bfloat16 g_Wvlo[HDIM * EDIM];
__device__ __nv_bfloat16 g_WqThi[EDIM * HDIM];      // Wq^T: [e][h]
__device__ __nv_bfloat16 g_WqTlo[EDIM * HDIM];
__device__ __nv_bfloat16 g_WkThi[EDIM * HDIM];
__device__ __nv_bfloat16 g_WkTlo[EDIM * HDIM];
__device__ __nv_bfloat16 g_Mhi[EDIM * EDIM];        // M^T stored [e'][e]
__device__ __nv_bfloat16 g_Mlo[EDIM * EDIM];
__device__ __nv_bfloat16 g_Qkhi[ML * EDIM];         // Qk = X*M^T
__device__ __nv_bfloat16 g_Qklo[ML * EDIM];
__device__ float         g_V[ML * HDIM];            // 64 MB
__device__ float         g_w1[EDIM];                // Wq^T * bk
__device__ float         g_w2[EDIM];                // Wk^T * bq
__device__ float         g_alpha[ML];               // X * w1
__device__ float         g_beta[ML];                // X * w2
__device__ float         g_c;                       // bq . bk
__device__ float         g_colsum[ML];
__device__ float         g_diag[ML];

// ---------------- helpers --------------------------------------------------
__device__ __forceinline__ uint32_t smem_u32(const void* p) {
    uint32_t a;
    asm("{ .reg .u64 t; cvta.to.shared.u64 t, %1; cvt.u32.u64 %0, t; }"
        : "=r"(a) : "l"(p));
    return a;
}

__device__ __forceinline__ void cp16(uint32_t s, const void* g) {
    asm volatile("cp.async.cg.shared.global [%0], [%1], 16;" :: "r"(s), "l"(g));
}
#define CP_COMMIT() asm volatile("cp.async.commit_group;" ::: "memory")
#define CP_WAIT2()  asm volatile("cp.async.wait_group 2;" ::: "memory")
#define CP_WAIT1()  asm volatile("cp.async.wait_group 1;" ::: "memory")
#define CP_WAIT0()  asm volatile("cp.async.wait_group 0;" ::: "memory")

__device__ __forceinline__ void ldsm4(uint32_t* a, uint32_t addr) {
    asm volatile("ldmatrix.sync.aligned.m8n8.x4.shared.b16 {%0,%1,%2,%3}, [%4];"
                 : "=r"(a[0]), "=r"(a[1]), "=r"(a[2]), "=r"(a[3]) : "r"(addr));
}
__device__ __forceinline__ void ldsm2(uint32_t* b, uint32_t addr) {
    asm volatile("ldmatrix.sync.aligned.m8n8.x2.shared.b16 {%0,%1}, [%2];"
                 : "=r"(b[0]), "=r"(b[1]) : "r"(addr));
}
__device__ __forceinline__ void mma16816(float* d, const uint32_t* a, const uint32_t* b) {
    asm volatile(
        "mma.sync.aligned.m16n8k16.row.col.f32.bf16.bf16.f32 "
        "{%0,%1,%2,%3}, {%4,%5,%6,%7}, {%8,%9}, {%0,%1,%2,%3};"
        : "+f"(d[0]), "+f"(d[1]), "+f"(d[2]), "+f"(d[3])
        : "r"(a[0]), "r"(a[1]), "r"(a[2]), "r"(a[3]), "r"(b[0]), "r"(b[1]));
}
// int8 IMMA, k32, s32 accumulate (Turing+; rock-solid on sm_103)
__device__ __forceinline__ void mma16832s8(int* d, const uint32_t* a, const uint32_t* b) {
    asm volatile(
        "mma.sync.aligned.m16n8k32.row.col.s32.s8.s8.s32 "
        "{%0,%1,%2,%3}, {%4,%5,%6,%7}, {%8,%9}, {%0,%1,%2,%3};"
        : "+r"(d[0]), "+r"(d[1]), "+r"(d[2]), "+r"(d[3])
        : "r"(a[0]), "r"(a[1]), "r"(a[2]), "r"(a[3]), "r"(b[0]), "r"(b[1]));
}

__device__ __forceinline__ int q8(float v) {
    int i = __float2int_rn(v * QSCALE);
    return max(-127, min(127, i));
}
__device__ __forceinline__ uint32_t pack4_s8(float a, float b, float c, float d) {
    return (uint32_t)(q8(a) & 0xff) | ((uint32_t)(q8(b) & 0xff) << 8) |
           ((uint32_t)(q8(c) & 0xff) << 16) | ((uint32_t)(q8(d) & 0xff) << 24);
}

// ---------------- tiling constants -----------------------------------------
#define PITCH   80                    // bytes/row: bf16 32 elems or s8 64 elems, + 16B pad
#define TSZ     (128 * PITCH)         // one operand tile: 10240 B
#define STG3    (4 * TSZ)             // 3-term stage: Ah, Al, Bh, Bl = 40960 B
#define STG8    (2 * TSZ)             // s8 stage: A8, B8 = 20480 B
#define DYNSMEM (2 * STG3)            // 81920 B (== 4 * STG8)

// ---------------------------------------------------------------------------
// run_tile3: 128x128 tile, split-bf16, 2-stage pipe, term-outer mma order.
// ---------------------------------------------------------------------------
__device__ __forceinline__ void run_tile3(
    const __nv_bfloat16* __restrict__ Ah, const __nv_bfloat16* __restrict__ Al,
    const __nv_bfloat16* __restrict__ Bh, const __nv_bfloat16* __restrict__ Bl,
    int m0, int n0, int Kdim, char* sm, float (&acc)[4][4][4])
{
    const int tid  = threadIdx.x;
    const int wid  = tid >> 5, lane = tid & 31;
    const int wm   = wid >> 2, wn = wid & 3;
    const uint32_t sbase = smem_u32(sm);

    const int r  = tid >> 1, cg = tid & 1;
    const size_t ga = (size_t)(m0 + r) * Kdim + cg * 16;
    const size_t gb = (size_t)(n0 + r) * Kdim + cg * 16;
    const uint32_t soff = (uint32_t)(r * PITCH + cg * 32);

    const uint32_t aoff = (uint32_t)((wm * 64 + (lane & 15)) * PITCH + (lane >> 4) * 16);
    const uint32_t boff = (uint32_t)((wn * 32 + (lane & 7)) * PITCH + ((lane >> 3) & 1) * 16);

#define LOADC3(st, kc) do {                                                   \
    const uint32_t s0 = sbase + (uint32_t)(st) * STG3 + soff;                 \
    cp16(s0 + 0 * TSZ,      Ah + ga + (kc));                                  \
    cp16(s0 + 0 * TSZ + 16, Ah + ga + (kc) + 8);                              \
    cp16(s0 + 1 * TSZ,      Al + ga + (kc));                                  \
    cp16(s0 + 1 * TSZ + 16, Al + ga + (kc) + 8);                              \
    cp16(s0 + 2 * TSZ,      Bh + gb + (kc));                                  \
    cp16(s0 + 2 * TSZ + 16, Bh + gb + (kc) + 8);                              \
    cp16(s0 + 3 * TSZ,      Bl + gb + (kc));                                  \
    cp16(s0 + 3 * TSZ + 16, Bl + gb + (kc) + 8);                              \
    CP_COMMIT();                                                              \
} while (0)

    const int NC = Kdim / 32;
    LOADC3(0, 0);

#pragma unroll 1
    for (int c = 0; c < NC; c++) {
        if (c + 1 < NC) { LOADC3((c + 1) & 1, (c + 1) * 32); CP_WAIT1(); }
        else            { CP_WAIT0(); }
        __syncthreads();

        const uint32_t tb = sbase + (uint32_t)(c & 1) * STG3;
#pragma unroll
        for (int k16 = 0; k16 < 2; k16++) {
            uint32_t ah[4][4], al[4][4], bh[4][2], bl[4][2];
#pragma unroll
            for (int mi = 0; mi < 4; mi++) {
                ldsm4(ah[mi], tb + 0 * TSZ + aoff + mi * 16 * PITCH + k16 * 32);
                ldsm4(al[mi], tb + 1 * TSZ + aoff + mi * 16 * PITCH + k16 * 32);
            }
#pragma unroll
            for (int ni = 0; ni < 4; ni++) {
                ldsm2(bh[ni], tb + 2 * TSZ + boff + ni * 8 * PITCH + k16 * 32);
                ldsm2(bl[ni], tb + 3 * TSZ + boff + ni * 8 * PITCH + k16 * 32);
            }
#pragma unroll
            for (int mi = 0; mi < 4; mi++)
#pragma unroll
                for (int ni = 0; ni < 4; ni++)
                    mma16816(acc[mi][ni], ah[mi], bh[ni]);
#pragma unroll
            for (int mi = 0; mi < 4; mi++)
#pragma unroll
                for (int ni = 0; ni < 4; ni++)
                    mma16816(acc[mi][ni], ah[mi], bl[ni]);
#pragma unroll
            for (int mi = 0; mi < 4; mi++)
#pragma unroll
                for (int ni = 0; ni < 4; ni++)
                    mma16816(acc[mi][ni], al[mi], bh[ni]);
        }
        __syncthreads();
    }
#undef LOADC3
}

// ---------------------------------------------------------------------------
// run_tile_i8: 128x128 tile, s8 IMMA k32, 4-stage pipe (mirror of proven
// run_tile1; s8-k32 fragments are byte-identical to bf16-k16 ldmatrix layout).
// ---------------------------------------------------------------------------
__device__ __forceinline__ void run_tile_i8(
    const uint8_t* __restrict__ A8, const uint8_t* __restrict__ B8,
    int m0, int n0, int Kdim, char* sm, int (&acc)[4][4][4])
{
    const int tid  = threadIdx.x;
    const int wid  = tid >> 5, lane = tid & 31;
    const int wm   = wid >> 2, wn = wid & 3;
    const uint32_t sbase = smem_u32(sm);

    const int r  = tid >> 1, cg = tid & 1;                 // row, 32B half
    const size_t ga = (size_t)(m0 + r) * Kdim + cg * 32;   // bytes == elems
    const size_t gb = (size_t)(n0 + r) * Kdim + cg * 32;
    const uint32_t soff = (uint32_t)(r * PITCH + cg * 32);

    const uint32_t aoff = (uint32_t)((wm * 64 + (lane & 15)) * PITCH + (lane >> 4) * 16);
    const uint32_t boff = (uint32_t)((wn * 32 + (lane & 7)) * PITCH + ((lane >> 3) & 1) * 16);

#define LOADC8(st, kc) do {                                                   \
    const uint32_t s0 = sbase + (uint32_t)(st) * STG8 + soff;                 \
    cp16(s0,            A8 + ga + (kc));                                      \
    cp16(s0 + 16,       A8 + ga + (kc) + 16);                                 \
    cp16(s0 + TSZ,      B8 + gb + (kc));                                      \
    cp16(s0 + TSZ + 16, B8 + gb + (kc) + 16);                                 \
    CP_COMMIT();                                                              \
} while (0)

    const int NC = Kdim / 64;           // 16 chunks of 64 s8
    LOADC8(0, 0);
    LOADC8(1, 64);
    LOADC8(2, 128);

#pragma unroll 1
    for (int c = 0; c < NC; c++) {
        CP_WAIT2();
        __syncthreads();
        const uint32_t tb = sbase + (uint32_t)(c & 3) * STG8;

#pragma unroll
        for (int s = 0; s < 2; s++) {                      // two k32 steps
            uint32_t a8[4][4], b8[4][2];
#pragma unroll
            for (int mi = 0; mi < 4; mi++)
                ldsm4(a8[mi], tb + aoff + mi * 16 * PITCH + s * 32);
#pragma unroll
            for (int ni = 0; ni < 4; ni++)
                ldsm2(b8[ni], tb + TSZ + boff + ni * 8 * PITCH + s * 32);
#pragma unroll
            for (int mi = 0; mi < 4; mi++)
#pragma unroll
                for (int ni = 0; ni < 4; ni++)
                    mma16832s8(acc[mi][ni], a8[mi], b8[ni]);
        }

        if (c + 3 < NC) LOADC8((c + 3) & 3, (c + 3) * 64);
    }
#undef LOADC8
}

// ---------------------------------------------------------------------------
// Conversions / transposes
// ---------------------------------------------------------------------------
__device__ __forceinline__ void split4(float4 v, __nv_bfloat162& h0, __nv_bfloat162& h1,
                                       __nv_bfloat162& l0, __nv_bfloat162& l1) {
    float f[4] = {v.x, v.y, v.z, v.w};
    __nv_bfloat16 h[4], l[4];
#pragma unroll
    for (int i = 0; i < 4; i++) {
        h[i] = __float2bfloat16(f[i]);
        l[i] = __float2bfloat16(f[i] - __bfloat162float(h[i]));
    }
    h0.x = h[0]; h0.y = h[1]; h1.x = h[2]; h1.y = h[3];
    l0.x = l[0]; l0.y = l[1]; l1.x = l[2]; l1.y = l[3];
}

__global__ void __launch_bounds__(256) convx_kernel(const float* __restrict__ X) {
    const size_t i = (size_t)blockIdx.x * 256 + threadIdx.x;
    float4 v = ((const float4*)X)[i];
    __nv_bfloat162 h0, h1, l0, l1;
    split4(v, h0, h1, l0, l1);
    ((__nv_bfloat162*)g_Xhi)[2 * i]     = h0;
    ((__nv_bfloat162*)g_Xhi)[2 * i + 1] = h1;
    ((__nv_bfloat162*)g_Xlo)[2 * i]     = l0;
    ((__nv_bfloat162*)g_Xlo)[2 * i + 1] = l1;
    ((uint32_t*)g_X8)[i] = pack4_s8(v.x, v.y, v.z, v.w);
}

__global__ void __launch_bounds__(256) convv_kernel(const float* __restrict__ Wv) {
    const size_t i = (size_t)blockIdx.x * 256 + threadIdx.x;
    float4 v = ((const float4*)Wv)[i];
    __nv_bfloat162 h0, h1, l0, l1;
    split4(v, h0, h1, l0, l1);
    ((__nv_bfloat162*)g_Wvhi)[2 * i]     = h0;
    ((__nv_bfloat162*)g_Wvhi)[2 * i + 1] = h1;
    ((__nv_bfloat162*)g_Wvlo)[2 * i]     = l0;
    ((__nv_bfloat162*)g_Wvlo)[2 * i + 1] = l1;
}

// Transposed split copies of Wq, Wk: WT[e][h] = W[h][e], bf16 hi/lo.
__global__ void __launch_bounds__(256) transw_kernel(
    const float* __restrict__ Wq, const float* __restrict__ Wk)
{
    __shared__ float t[32][33];
    const int z = blockIdx.z;
    const float* W = z ? Wk : Wq;
    __nv_bfloat16* Th = z ? g_WkThi : g_WqThi;
    __nv_bfloat16* Tl = z ? g_WkTlo : g_WqTlo;
    const int e0 = blockIdx.x * 32, h0 = blockIdx.y * 32;
    const int tx = threadIdx.x & 31, ty = threadIdx.x >> 5;  // 32 x 8

#pragma unroll
    for (int i = ty; i < 32; i += 8)
        t[i][tx] = W[(size_t)(h0 + i) * EDIM + e0 + tx];
    __syncthreads();
#pragma unroll
    for (int i = ty; i < 32; i += 8) {
        float v = t[tx][i];                 // = W[h0+tx][e0+i]
        __nv_bfloat16 h = __float2bfloat16(v);
        __nv_bfloat16 l = __float2bfloat16(v - __bfloat162float(h));
        Th[(size_t)(e0 + i) * HDIM + h0 + tx] = h;
        Tl[(size_t)(e0 + i) * HDIM + h0 + tx] = l;
    }
}

// w1[e] = sum_h Wq[h,e]*bk[h],  w2[e] = sum_h Wk[h,e]*bq[h]
__global__ void __launch_bounds__(256) biasw_kernel(
    const float* __restrict__ bq, const float* __restrict__ bk)
{
    __shared__ float red[8];
    const int e = blockIdx.x, z = blockIdx.y;
    const __nv_bfloat16* Th = z ? g_WkThi : g_WqThi;
    const __nv_bfloat16* Tl = z ? g_WkTlo : g_WqTlo;
    const float* b = z ? bq : bk;
    float s = 0.0f;
    for (int h = threadIdx.x; h < HDIM; h += 256)
        s += (__bfloat162float(Th[(size_t)e * HDIM + h]) +
              __bfloat162float(Tl[(size_t)e * HDIM + h])) * b[h];
#pragma unroll
    for (int m = 16; m >= 1; m >>= 1) s += __shfl_xor_sync(0xffffffffu, s, m);
    if ((threadIdx.x & 31) == 0) red[threadIdx.x >> 5] = s;
    __syncthreads();
    if (threadIdx.x == 0) {
        float t = 0.0f;
#pragma unroll
        for (int i = 0; i < 8; i++) t += red[i];
        (z ? g_w2 : g_w1)[e] = t;
    }
}

__global__ void cscalar_kernel(const float* __restrict__ bq,
                               const float* __restrict__ bk)
{
    __shared__ float red[8];
    float s = 0.0f;
    for (int h = threadIdx.x; h < HDIM; h += 256) s += bq[h] * bk[h];
#pragma unroll
    for (int m = 16; m >= 1; m >>= 1) s += __shfl_xor_sync(0xffffffffu, s, m);
    if ((threadIdx.x & 31) == 0) red[threadIdx.x >> 5] = s;
    __syncthreads();
    if (threadIdx.x == 0) {
        float t = 0.0f;
#pragma unroll
        for (int i = 0; i < 8; i++) t += red[i];
        g_c = t;
    }
}

// alpha[l] = X[l].w1, beta[l] = X[l].w2  (exact fp32 inputs)
__global__ void __launch_bounds__(256) alphabeta_kernel(const float* __restrict__ X)
{
    __shared__ float reda[8], redb[8];
    const int l = blockIdx.x;
    float sa = 0.0f, sb = 0.0f;
    for (int e = threadIdx.x; e < EDIM; e += 256) {
        float x = X[(size_t)l * EDIM + e];
        sa += x * g_w1[e];
        sb += x * g_w2[e];
    }
#pragma unroll
    for (int m = 16; m >= 1; m >>= 1) {
        sa += __shfl_xor_sync(0xffffffffu, sa, m);
        sb += __shfl_xor_sync(0xffffffffu, sb, m);
    }
    if ((threadIdx.x & 31) == 0) { reda[threadIdx.x >> 5] = sa; redb[threadIdx.x >> 5] = sb; }
    __syncthreads();
    if (threadIdx.x == 0) {
        float ta = 0.0f, tb = 0.0f;
#pragma unroll
        for (int i = 0; i < 8; i++) { ta += reda[i]; tb += redb[i]; }
        g_alpha[l] = ta;
        g_beta[l]  = tb;
    }
}

// ---------------------------------------------------------------------------
// mgemm: Mt[e'][e] = sum_h Wk[h,e']*Wq[h,e]  (3-term).  grid (8, 8)
// ---------------------------------------------------------------------------
__global__ void __launch_bounds__(256, 2) mgemm_kernel()
{
    extern __shared__ char dynsm[];
    const int m0 = blockIdx.y * 128;   // e'
    const int n0 = blockIdx.x * 128;   // e

    float acc[4][4][4];
#pragma unroll
    for (int a = 0; a < 4; a++)
#pragma unroll
        for (int b = 0; b < 4; b++)
#pragma unroll
            for (int cc = 0; cc < 4; cc++) acc[a][b][cc] = 0.0f;

    run_tile3(g_WkThi, g_WkTlo, g_WqThi, g_WqTlo, m0, n0, HDIM, dynsm, acc);

    const int tid = threadIdx.x;
    const int wid = tid >> 5, lane = tid & 31;
    const int wm = wid >> 2, wn = wid & 3;

#pragma unroll
    for (int mi = 0; mi < 4; mi++) {
        const int r0 = m0 + wm * 64 + mi * 16 + (lane >> 2);
#pragma unroll
        for (int ni = 0; ni < 4; ni++) {
            const int gc = n0 + wn * 32 + ni * 8 + 2 * (lane & 3);
#pragma unroll
            for (int hh = 0; hh < 2; hh++) {
                const int rr = r0 + hh * 8;
                const float v0 = acc[mi][ni][2 * hh], v1 = acc[mi][ni][2 * hh + 1];
                __nv_bfloat162 h2, l2;
                h2.x = __float2bfloat16(v0);
                h2.y = __float2bfloat16(v1);
                l2.x = __float2bfloat16(v0 - __bfloat162float(h2.x));
                l2.y = __float2bfloat16(v1 - __bfloat162float(h2.y));
                *(__nv_bfloat162*)(g_Mhi + (size_t)rr * EDIM + gc) = h2;
                *(__nv_bfloat162*)(g_Mlo + (size_t)rr * EDIM + gc) = l2;
            }
        }
    }
}

// ---------------------------------------------------------------------------
// GEMM1: z=0: Qk = X*M^T (bf16 hi/lo + s8 out);  z=1: V = X*Wv^T + bv
// grid (8, 128, 2)
// ---------------------------------------------------------------------------
__global__ void __launch_bounds__(256, 2) gemm1_kernel(const float* __restrict__ bv)
{
    extern __shared__ char dynsm[];
    const int z  = blockIdx.z;
    const int m0 = blockIdx.y * 128;
    const int n0 = blockIdx.x * 128;

    const __nv_bfloat16* Bh = z ? g_Wvhi : g_Mhi;
    const __nv_bfloat16* Bl = z ? g_Wvlo : g_Mlo;

    float acc[4][4][4];
#pragma unroll
    for (int a = 0; a < 4; a++)
#pragma unroll
        for (int b = 0; b < 4; b++)
#pragma unroll
            for (int cc = 0; cc < 4; cc++) acc[a][b][cc] = 0.0f;

    run_tile3(g_Xhi, g_Xlo, Bh, Bl, m0, n0, EDIM, dynsm, acc);

    const int tid = threadIdx.x;
    const int wid = tid >> 5, lane = tid & 31;
    const int wm = wid >> 2, wn = wid & 3;

#pragma unroll
    for (int mi = 0; mi < 4; mi++) {
        const int r0 = m0 + wm * 64 + mi * 16 + (lane >> 2);
#pragma unroll
        for (int ni = 0; ni < 4; ni++) {
            const int gc = n0 + wn * 32 + ni * 8 + 2 * (lane & 3);
            if (z == 1) {
                const float b0 = __ldg(&bv[gc]), b1 = __ldg(&bv[gc + 1]);
                *(float2*)(g_V + (size_t)r0 * HDIM + gc) =
                    make_float2(acc[mi][ni][0] + b0, acc[mi][ni][1] + b1);
                *(float2*)(g_V + (size_t)(r0 + 8) * HDIM + gc) =
                    make_float2(acc[mi][ni][2] + b0, acc[mi][ni][3] + b1);
            } else {
#pragma unroll
                for (int hh = 0; hh < 2; hh++) {
                    const int rr = r0 + hh * 8;
                    const float v0 = acc[mi][ni][2 * hh], v1 = acc[mi][ni][2 * hh + 1];
                    __nv_bfloat162 h2, l2;
                    h2.x = __float2bfloat16(v0);
                    h2.y = __float2bfloat16(v1);
                    l2.x = __float2bfloat16(v0 - __bfloat162float(h2.x));
                    l2.y = __float2bfloat16(v1 - __bfloat162float(h2.y));
                    *(__nv_bfloat162*)(g_Qkhi + (size_t)rr * EDIM + gc) = h2;
                    *(__nv_bfloat162*)(g_Qklo + (size_t)rr * EDIM + gc) = l2;
                    const uint16_t p = (uint16_t)((q8(v0) & 0xff) | ((q8(v1) & 0xff) << 8));
                    *(uint16_t*)(g_Qk8 + (size_t)rr * EDIM + gc) = p;
                }
            }
        }
    }
}

// ---------------------------------------------------------------------------
// Scores epilogue helper: exp + colsum (+ optional diag), with alpha/beta/c.
// ---------------------------------------------------------------------------
__device__ __forceinline__ void scores_epilogue(
    float (&acc)[4][4][4], int bz, int m0, int n0, bool diagblk)
{
    __shared__ float sred[128];
    const int tid = threadIdx.x;
    const int wid = tid >> 5, lane = tid & 31;
    const int wm = wid >> 2, wn = wid & 3;
    const float sc = 0.015625f;   // 1/sqrt(4096)
    const float cc = g_c;

    if (tid < 128) sred[tid] = 0.0f;

    float2 csum[4];
#pragma unroll
    for (int ni = 0; ni < 4; ni++) csum[ni] = make_float2(0.0f, 0.0f);

#pragma unroll
    for (int mi = 0; mi < 4; mi++) {
        const int lr = wm * 64 + mi * 16 + (lane >> 2);
        const float a0 = g_alpha[(size_t)bz * LSEQ + m0 + lr];
        const float a1 = g_alpha[(size_t)bz * LSEQ + m0 + lr + 8];
#pragma unroll
        for (int ni = 0; ni < 4; ni++) {
            const int lc = wn * 32 + ni * 8 + 2 * (lane & 3);
            const float b0 = g_beta[(size_t)bz * LSEQ + n0 + lc];
            const float b1 = g_beta[(size_t)bz * LSEQ + n0 + lc + 1];
            const float e00 = __expf((acc[mi][ni][0] + a0 + b0 + cc) * sc);
            const float e01 = __expf((acc[mi][ni][1] + a0 + b1 + cc) * sc);
            const float e10 = __expf((acc[mi][ni][2] + a1 + b0 + cc) * sc);
            const float e11 = __expf((acc[mi][ni][3] + a1 + b1 + cc) * sc);
            csum[ni].x += e00 + e10;
            csum[ni].y += e01 + e11;
            if (diagblk) {
                if (lr == lc)         g_diag[(size_t)bz * LSEQ + m0 + lr] = e00;
                if (lr == lc + 1)     g_diag[(size_t)bz * LSEQ + m0 + lr] = e01;
                if (lr + 8 == lc)     g_diag[(size_t)bz * LSEQ + m0 + lr + 8] = e10;
                if (lr + 8 == lc + 1) g_diag[(size_t)bz * LSEQ + m0 + lr + 8] = e11;
            }
        }
    }

    __syncthreads();   // sred init visible

#pragma unroll
    for (int ni = 0; ni < 4; ni++) {
#pragma unroll
        for (int m = 4; m <= 16; m <<= 1) {
            csum[ni].x += __shfl_xor_sync(0xffffffffu, csum[ni].x, m);
            csum[ni].y += __shfl_xor_sync(0xffffffffu, csum[ni].y, m);
        }
        if (lane < 4) {
            atomicAdd(&sred[wn * 32 + ni * 8 + 2 * lane],     csum[ni].x);
            atomicAdd(&sred[wn * 32 + ni * 8 + 2 * lane + 1], csum[ni].y);
        }
    }

    __syncthreads();
    if (tid < 128)
        atomicAdd(&g_colsum[(size_t)bz * LSEQ + n0 + tid], sred[tid]);
}

// ---------------------------------------------------------------------------
// GEMM2 off-diagonal: S = Qk8 * X8^T (s8 IMMA, exact s32 accum).
// grid (32, 32, NB)
// ---------------------------------------------------------------------------
__global__ void __launch_bounds__(256) gemm2_off_kernel()
{
    if (blockIdx.x == blockIdx.y) return;   // diag handled separately
    extern __shared__ char dynsm[];

    const int bz = blockIdx.z;
    const int m0 = blockIdx.y * 128;
    const int n0 = blockIdx.x * 128;
    const size_t bo = (size_t)bz * LSEQ * EDIM;

    int acci[4][4][4];
#pragma unroll
    for (int a = 0; a < 4; a++)
#pragma unroll
        for (int b = 0; b < 4; b++)
#pragma unroll
            for (int cc = 0; cc < 4; cc++) acci[a][b][cc] = 0;

    run_tile_i8(g_Qk8 + bo, g_X8 + bo, m0, n0, EDIM, dynsm, acci);

    float acc[4][4][4];
#pragma unroll
    for (int a = 0; a < 4; a++)
#pragma unroll
        for (int b = 0; b < 4; b++)
#pragma unroll
            for (int cc = 0; cc < 4; cc++)
                acc[a][b][cc] = (float)acci[a][b][cc] * QSCALE_I2;

    scores_epilogue(acc, bz, m0, n0, false);
}

// ---------------------------------------------------------------------------
// GEMM2 diagonal: 3-term bf16 split, diag extraction.  grid (32, NB)
// ---------------------------------------------------------------------------
__global__ void __launch_bounds__(256, 2) gemm2_diag_kernel()
{
    extern __shared__ char dynsm[];
    const int bz = blockIdx.y;
    const int m0 = blockIdx.x * 128;
    const size_t bo = (size_t)bz * LSEQ * EDIM;

    float acc[4][4][4];
#pragma unroll
    for (int a = 0; a < 4; a++)
#pragma unroll
        for (int b = 0; b < 4; b++)
#pragma unroll
            for (int cc = 0; cc < 4; cc++) acc[a][b][cc] = 0.0f;

    run_tile3(g_Qkhi + bo, g_Qklo + bo, g_Xhi + bo, g_Xlo + bo,
              m0, m0, EDIM, dynsm, acc);
    scores_epilogue(acc, bz, m0, m0, true);
}

// ---------------------------------------------------------------------------
__global__ void __launch_bounds__(256) finalize_kernel(float* __restrict__ out)
{
    const int row = blockIdx.x;
    const float scale = g_diag[row] / g_colsum[row];
    const float4* v = (const float4*)(g_V + (size_t)row * HDIM);
    float4* o = (float4*)(out + (size_t)row * HDIM);
    float4 x = v[threadIdx.x];
    x.x *= scale; x.y *= scale; x.z *= scale; x.w *= scale;
    o[threadIdx.x] = x;
}

__global__ void zero_kernel()
{
    const int i = blockIdx.x * 256 + threadIdx.x;
    if (i < ML) g_colsum[i] = 0.0f;
}

// ---------------------------------------------------------------------------
extern "C" void kernel_launch(void* const* d_in, const int* in_sizes, int n_in,
                              void* d_out, int out_size)
{
    (void)in_sizes; (void)n_in; (void)out_size;
    const float* X  = (const float*)d_in[0];
    const float* Wq = (const float*)d_in[1];
    const float* bq = (const float*)d_in[2];
    const float* Wk = (const float*)d_in[3];
    const float* bk = (const float*)d_in[4];
    const float* Wv = (const float*)d_in[5];
    const float* bv = (const float*)d_in[6];
    float* out = (float*)d_out;

    // Idempotent host-side attribute setup (capture-safe, not stream ops).
    cudaFuncSetAttribute(mgemm_kernel,      cudaFuncAttributeMaxDynamicSharedMemorySize, DYNSMEM);
    cudaFuncSetAttribute(gemm1_kernel,      cudaFuncAttributeMaxDynamicSharedMemorySize, DYNSMEM);
    cudaFuncSetAttribute(gemm2_off_kernel,  cudaFuncAttributeMaxDynamicSharedMemorySize, DYNSMEM);
    cudaFuncSetAttribute(gemm2_diag_kernel, cudaFuncAttributeMaxDynamicSharedMemorySize, DYNSMEM);
    cudaFuncSetAttribute(mgemm_kernel,      cudaFuncAttributePreferredSharedMemoryCarveout, 100);
    cudaFuncSetAttribute(gemm1_kernel,      cudaFuncAttributePreferredSharedMemoryCarveout, 100);
    cudaFuncSetAttribute(gemm2_off_kernel,  cudaFuncAttributePreferredSharedMemoryCarveout, 100);
    cudaFuncSetAttribute(gemm2_diag_kernel, cudaFuncAttributePreferredSharedMemoryCarveout, 100);

    zero_kernel<<<(ML + 255) / 256, 256>>>();

    convx_kernel<<<(ML * EDIM / 4) / 256, 256>>>(X);
    convv_kernel<<<(HDIM * EDIM / 4) / 256, 256>>>(Wv);

    dim3 gt(EDIM / 32, HDIM / 32, 2);
    transw_kernel<<<gt, 256>>>(Wq, Wk);

    dim3 gb(EDIM, 2);
    biasw_kernel<<<gb, 256>>>(bq, bk);
    cscalar_kernel<<<1, 256>>>(bq, bk);

    dim3 gm(EDIM / 128, EDIM / 128);
    mgemm_kernel<<<gm, 256, DYNSMEM>>>();

    alphabeta_kernel<<<ML, 256>>>(X);

    dim3 g1(EDIM / 128, ML / 128, 2);
    gemm1_kernel<<<g1, 256, DYNSMEM>>>(bv);

    dim3 g2(LSEQ / 128, LSEQ / 128, NB);
    gemm2_off_kernel<<<g2, 256, DYNSMEM>>>();

    dim3 g2d(LSEQ / 128, NB);
    gemm2_diag_kernel<<<g2d, 256, DYNSMEM>>>();

    finalize_kernel<<<ML, 256>>>(out);
}

// round 13
// speedup vs baseline: 1.3786x; 1.3786x over previous
#include <cuda_runtime.h>
#include <cuda_bf16.h>
#include <cuda_fp16.h>
#include <math.h>
#include <stdint.h>

#define NB   4
#define LSEQ 4096
#define EDIM 1024
#define HDIM 1024
#define ML   (NB * LSEQ)      // 16384

// ---------------- scratch (static device arrays; no allocation APIs) -------
__device__ __nv_bfloat16 g_Xhi[ML * EDIM];          // 32 MB
__device__ __nv_bfloat16 g_Xlo[ML * EDIM];
__device__ __half        g_X16[ML * EDIM];          // 32 MB fp16 copy of X
__device__ __half        g_Qk16[ML * EDIM];         // 32 MB fp16 copy of Qk
__device__ __nv_bfloat16 g_Wvhi[HDIM * EDIM];
__device__ __nv_bfloat16 g_Wvlo[HDIM * EDIM];
__device__ __nv_bfloat16 g_WqThi[EDIM * HDIM];      // Wq^T: [e][h]
__device__ __nv_bfloat16 g_WqTlo[EDIM * HDIM];
__device__ __nv_bfloat16 g_WkThi[EDIM * HDIM];
__device__ __nv_bfloat16 g_WkTlo[EDIM * HDIM];
__device__ __nv_bfloat16 g_Mhi[EDIM * EDIM];        // M^T stored [e'][e]
__device__ __nv_bfloat16 g_Mlo[EDIM * EDIM];
__device__ __nv_bfloat16 g_Qkhi[ML * EDIM];         // Qk = X*M^T
__device__ __nv_bfloat16 g_Qklo[ML * EDIM];
__device__ float         g_V[ML * HDIM];            // 64 MB
__device__ float         g_w1[EDIM];                // Wq^T * bk
__device__ float         g_w2[EDIM];                // Wk^T * bq
__device__ float         g_alpha[ML];               // X * w1
__device__ float         g_beta[ML];                // X * w2
__device__ float         g_c;                       // bq . bk
__device__ float         g_colsum[ML];
__device__ float         g_diag[ML];

// ---------------- helpers --------------------------------------------------
__device__ __forceinline__ uint32_t smem_u32(const void* p) {
    uint32_t a;
    asm("{ .reg .u64 t; cvta.to.shared.u64 t, %1; cvt.u32.u64 %0, t; }"
        : "=r"(a) : "l"(p));
    return a;
}

__device__ __forceinline__ void cp16(uint32_t s, const void* g) {
    asm volatile("cp.async.cg.shared.global [%0], [%1], 16;" :: "r"(s), "l"(g));
}
#define CP_COMMIT() asm volatile("cp.async.commit_group;" ::: "memory")
#define CP_WAIT2()  asm volatile("cp.async.wait_group 2;" ::: "memory")
#define CP_WAIT1()  asm volatile("cp.async.wait_group 1;" ::: "memory")
#define CP_WAIT0()  asm volatile("cp.async.wait_group 0;" ::: "memory")

__device__ __forceinline__ void ldsm4(uint32_t* a, uint32_t addr) {
    asm volatile("ldmatrix.sync.aligned.m8n8.x4.shared.b16 {%0,%1,%2,%3}, [%4];"
                 : "=r"(a[0]), "=r"(a[1]), "=r"(a[2]), "=r"(a[3]) : "r"(addr));
}
__device__ __forceinline__ void ldsm2(uint32_t* b, uint32_t addr) {
    asm volatile("ldmatrix.sync.aligned.m8n8.x2.shared.b16 {%0,%1}, [%2];"
                 : "=r"(b[0]), "=r"(b[1]) : "r"(addr));
}
__device__ __forceinline__ void mma16816(float* d, const uint32_t* a, const uint32_t* b) {
    asm volatile(
        "mma.sync.aligned.m16n8k16.row.col.f32.bf16.bf16.f32 "
        "{%0,%1,%2,%3}, {%4,%5,%6,%7}, {%8,%9}, {%0,%1,%2,%3};"
        : "+f"(d[0]), "+f"(d[1]), "+f"(d[2]), "+f"(d[3])
        : "r"(a[0]), "r"(a[1]), "r"(a[2]), "r"(a[3]), "r"(b[0]), "r"(b[1]));
}
// fp16 inputs, fp16 accumulate — the one mma.sync form with a potential 2x rate
__device__ __forceinline__ void mma16816h(uint32_t* d, const uint32_t* a, const uint32_t* b) {
    asm volatile(
        "mma.sync.aligned.m16n8k16.row.col.f16.f16.f16.f16 "
        "{%0,%1}, {%2,%3,%4,%5}, {%6,%7}, {%0,%1};"
        : "+r"(d[0]), "+r"(d[1])
        : "r"(a[0]), "r"(a[1]), "r"(a[2]), "r"(a[3]), "r"(b[0]), "r"(b[1]));
}

// ---------------- tiling constants -----------------------------------------
#define PITCH   80                    // bytes per smem row (32 halves + 16B pad)
#define TSZ     (128 * PITCH)         // one operand tile: 10240 B
#define STG3    (4 * TSZ)             // 3-term stage: Ah, Al, Bh, Bl = 40960 B
#define STG1    (2 * TSZ)             // 1-term stage: A, B = 20480 B
#define DYNSMEM (2 * STG3)            // 81920 B (== 4 * STG1)

// ---------------------------------------------------------------------------
// run_tile3: 128x128 tile, split-bf16, 2-stage pipe, term-outer mma order.
// ---------------------------------------------------------------------------
__device__ __forceinline__ void run_tile3(
    const __nv_bfloat16* __restrict__ Ah, const __nv_bfloat16* __restrict__ Al,
    const __nv_bfloat16* __restrict__ Bh, const __nv_bfloat16* __restrict__ Bl,
    int m0, int n0, int Kdim, char* sm, float (&acc)[4][4][4])
{
    const int tid  = threadIdx.x;
    const int wid  = tid >> 5, lane = tid & 31;
    const int wm   = wid >> 2, wn = wid & 3;
    const uint32_t sbase = smem_u32(sm);

    const int r  = tid >> 1, cg = tid & 1;
    const size_t ga = (size_t)(m0 + r) * Kdim + cg * 16;
    const size_t gb = (size_t)(n0 + r) * Kdim + cg * 16;
    const uint32_t soff = (uint32_t)(r * PITCH + cg * 32);

    const uint32_t aoff = (uint32_t)((wm * 64 + (lane & 15)) * PITCH + (lane >> 4) * 16);
    const uint32_t boff = (uint32_t)((wn * 32 + (lane & 7)) * PITCH + ((lane >> 3) & 1) * 16);

#define LOADC3(st, kc) do {                                                   \
    const uint32_t s0 = sbase + (uint32_t)(st) * STG3 + soff;                 \
    cp16(s0 + 0 * TSZ,      Ah + ga + (kc));                                  \
    cp16(s0 + 0 * TSZ + 16, Ah + ga + (kc) + 8);                              \
    cp16(s0 + 1 * TSZ,      Al + ga + (kc));                                  \
    cp16(s0 + 1 * TSZ + 16, Al + ga + (kc) + 8);                              \
    cp16(s0 + 2 * TSZ,      Bh + gb + (kc));                                  \
    cp16(s0 + 2 * TSZ + 16, Bh + gb + (kc) + 8);                              \
    cp16(s0 + 3 * TSZ,      Bl + gb + (kc));                                  \
    cp16(s0 + 3 * TSZ + 16, Bl + gb + (kc) + 8);                              \
    CP_COMMIT();                                                              \
} while (0)

    const int NC = Kdim / 32;
    LOADC3(0, 0);

#pragma unroll 1
    for (int c = 0; c < NC; c++) {
        if (c + 1 < NC) { LOADC3((c + 1) & 1, (c + 1) * 32); CP_WAIT1(); }
        else            { CP_WAIT0(); }
        __syncthreads();

        const uint32_t tb = sbase + (uint32_t)(c & 1) * STG3;
#pragma unroll
        for (int k16 = 0; k16 < 2; k16++) {
            uint32_t ah[4][4], al[4][4], bh[4][2], bl[4][2];
#pragma unroll
            for (int mi = 0; mi < 4; mi++) {
                ldsm4(ah[mi], tb + 0 * TSZ + aoff + mi * 16 * PITCH + k16 * 32);
                ldsm4(al[mi], tb + 1 * TSZ + aoff + mi * 16 * PITCH + k16 * 32);
            }
#pragma unroll
            for (int ni = 0; ni < 4; ni++) {
                ldsm2(bh[ni], tb + 2 * TSZ + boff + ni * 8 * PITCH + k16 * 32);
                ldsm2(bl[ni], tb + 3 * TSZ + boff + ni * 8 * PITCH + k16 * 32);
            }
#pragma unroll
            for (int mi = 0; mi < 4; mi++)
#pragma unroll
                for (int ni = 0; ni < 4; ni++)
                    mma16816(acc[mi][ni], ah[mi], bh[ni]);
#pragma unroll
            for (int mi = 0; mi < 4; mi++)
#pragma unroll
                for (int ni = 0; ni < 4; ni++)
                    mma16816(acc[mi][ni], ah[mi], bl[ni]);
#pragma unroll
            for (int mi = 0; mi < 4; mi++)
#pragma unroll
                for (int ni = 0; ni < 4; ni++)
                    mma16816(acc[mi][ni], al[mi], bh[ni]);
        }
        __syncthreads();
    }
#undef LOADC3
}

// ---------------------------------------------------------------------------
// run_tile_h: 128x128 tile, fp16 in / fp16 acc, 4-stage pipe, 1 sync/chunk.
// Structure is the long-proven run_tile1; only the mma + acc type changed.
// ---------------------------------------------------------------------------
__device__ __forceinline__ void run_tile_h(
    const __half* __restrict__ A, const __half* __restrict__ B,
    int m0, int n0, int Kdim, char* sm, uint32_t (&acc)[4][4][2])
{
    const int tid  = threadIdx.x;
    const int wid  = tid >> 5, lane = tid & 31;
    const int wm   = wid >> 2, wn = wid & 3;
    const uint32_t sbase = smem_u32(sm);

    const int r  = tid >> 1, cg = tid & 1;
    const size_t ga = (size_t)(m0 + r) * Kdim + cg * 16;
    const size_t gb = (size_t)(n0 + r) * Kdim + cg * 16;
    const uint32_t soff = (uint32_t)(r * PITCH + cg * 32);

    const uint32_t aoff = (uint32_t)((wm * 64 + (lane & 15)) * PITCH + (lane >> 4) * 16);
    const uint32_t boff = (uint32_t)((wn * 32 + (lane & 7)) * PITCH + ((lane >> 3) & 1) * 16);

#define LOADCH(st, kc) do {                                                   \
    const uint32_t s0 = sbase + (uint32_t)(st) * STG1 + soff;                 \
    cp16(s0,            A + ga + (kc));                                       \
    cp16(s0 + 16,       A + ga + (kc) + 8);                                   \
    cp16(s0 + TSZ,      B + gb + (kc));                                       \
    cp16(s0 + TSZ + 16, B + gb + (kc) + 8);                                   \
    CP_COMMIT();                                                              \
} while (0)

    const int NC = Kdim / 32;
    LOADCH(0, 0);
    LOADCH(1, 32);
    LOADCH(2, 64);

#pragma unroll 1
    for (int c = 0; c < NC; c++) {
        CP_WAIT2();
        __syncthreads();
        const uint32_t tb = sbase + (uint32_t)(c & 3) * STG1;
#pragma unroll
        for (int k16 = 0; k16 < 2; k16++) {
            uint32_t ah[4][4], bh[4][2];
#pragma unroll
            for (int mi = 0; mi < 4; mi++)
                ldsm4(ah[mi], tb + aoff + mi * 16 * PITCH + k16 * 32);
#pragma unroll
            for (int ni = 0; ni < 4; ni++)
                ldsm2(bh[ni], tb + TSZ + boff + ni * 8 * PITCH + k16 * 32);
#pragma unroll
            for (int mi = 0; mi < 4; mi++)
#pragma unroll
                for (int ni = 0; ni < 4; ni++)
                    mma16816h(acc[mi][ni], ah[mi], bh[ni]);
        }
        if (c + 3 < NC) LOADCH((c + 3) & 3, (c + 3) * 32);
    }
#undef LOADCH
}

// ---------------------------------------------------------------------------
// Conversions / transposes
// ---------------------------------------------------------------------------
__device__ __forceinline__ void split4(float4 v, __nv_bfloat162& h0, __nv_bfloat162& h1,
                                       __nv_bfloat162& l0, __nv_bfloat162& l1) {
    float f[4] = {v.x, v.y, v.z, v.w};
    __nv_bfloat16 h[4], l[4];
#pragma unroll
    for (int i = 0; i < 4; i++) {
        h[i] = __float2bfloat16(f[i]);
        l[i] = __float2bfloat16(f[i] - __bfloat162float(h[i]));
    }
    h0.x = h[0]; h0.y = h[1]; h1.x = h[2]; h1.y = h[3];
    l0.x = l[0]; l0.y = l[1]; l1.x = l[2]; l1.y = l[3];
}

__global__ void __launch_bounds__(256) convx_kernel(const float* __restrict__ X) {
    const size_t i = (size_t)blockIdx.x * 256 + threadIdx.x;
    float4 v = ((const float4*)X)[i];
    __nv_bfloat162 h0, h1, l0, l1;
    split4(v, h0, h1, l0, l1);
    ((__nv_bfloat162*)g_Xhi)[2 * i]     = h0;
    ((__nv_bfloat162*)g_Xhi)[2 * i + 1] = h1;
    ((__nv_bfloat162*)g_Xlo)[2 * i]     = l0;
    ((__nv_bfloat162*)g_Xlo)[2 * i + 1] = l1;
    ((__half2*)g_X16)[2 * i]     = __floats2half2_rn(v.x, v.y);
    ((__half2*)g_X16)[2 * i + 1] = __floats2half2_rn(v.z, v.w);
}

__global__ void __launch_bounds__(256) convv_kernel(const float* __restrict__ Wv) {
    const size_t i = (size_t)blockIdx.x * 256 + threadIdx.x;
    float4 v = ((const float4*)Wv)[i];
    __nv_bfloat162 h0, h1, l0, l1;
    split4(v, h0, h1, l0, l1);
    ((__nv_bfloat162*)g_Wvhi)[2 * i]     = h0;
    ((__nv_bfloat162*)g_Wvhi)[2 * i + 1] = h1;
    ((__nv_bfloat162*)g_Wvlo)[2 * i]     = l0;
    ((__nv_bfloat162*)g_Wvlo)[2 * i + 1] = l1;
}

// Transposed split copies of Wq, Wk: WT[e][h] = W[h][e], bf16 hi/lo.
__global__ void __launch_bounds__(256) transw_kernel(
    const float* __restrict__ Wq, const float* __restrict__ Wk)
{
    __shared__ float t[32][33];
    const int z = blockIdx.z;
    const float* W = z ? Wk : Wq;
    __nv_bfloat16* Th = z ? g_WkThi : g_WqThi;
    __nv_bfloat16* Tl = z ? g_WkTlo : g_WqTlo;
    const int e0 = blockIdx.x * 32, h0 = blockIdx.y * 32;
    const int tx = threadIdx.x & 31, ty = threadIdx.x >> 5;  // 32 x 8

#pragma unroll
    for (int i = ty; i < 32; i += 8)
        t[i][tx] = W[(size_t)(h0 + i) * EDIM + e0 + tx];
    __syncthreads();
#pragma unroll
    for (int i = ty; i < 32; i += 8) {
        float v = t[tx][i];                 // = W[h0+tx][e0+i]
        __nv_bfloat16 h = __float2bfloat16(v);
        __nv_bfloat16 l = __float2bfloat16(v - __bfloat162float(h));
        Th[(size_t)(e0 + i) * HDIM + h0 + tx] = h;
        Tl[(size_t)(e0 + i) * HDIM + h0 + tx] = l;
    }
}

// w1[e] = sum_h Wq[h,e]*bk[h],  w2[e] = sum_h Wk[h,e]*bq[h]
__global__ void __launch_bounds__(256) biasw_kernel(
    const float* __restrict__ bq, const float* __restrict__ bk)
{
    __shared__ float red[8];
    const int e = blockIdx.x, z = blockIdx.y;
    const __nv_bfloat16* Th = z ? g_WkThi : g_WqThi;
    const __nv_bfloat16* Tl = z ? g_WkTlo : g_WqTlo;
    const float* b = z ? bq : bk;
    float s = 0.0f;
    for (int h = threadIdx.x; h < HDIM; h += 256)
        s += (__bfloat162float(Th[(size_t)e * HDIM + h]) +
              __bfloat162float(Tl[(size_t)e * HDIM + h])) * b[h];
#pragma unroll
    for (int m = 16; m >= 1; m >>= 1) s += __shfl_xor_sync(0xffffffffu, s, m);
    if ((threadIdx.x & 31) == 0) red[threadIdx.x >> 5] = s;
    __syncthreads();
    if (threadIdx.x == 0) {
        float t = 0.0f;
#pragma unroll
        for (int i = 0; i < 8; i++) t += red[i];
        (z ? g_w2 : g_w1)[e] = t;
    }
}

__global__ void cscalar_kernel(const float* __restrict__ bq,
                               const float* __restrict__ bk)
{
    __shared__ float red[8];
    float s = 0.0f;
    for (int h = threadIdx.x; h < HDIM; h += 256) s += bq[h] * bk[h];
#pragma unroll
    for (int m = 16; m >= 1; m >>= 1) s += __shfl_xor_sync(0xffffffffu, s, m);
    if ((threadIdx.x & 31) == 0) red[threadIdx.x >> 5] = s;
    __syncthreads();
    if (threadIdx.x == 0) {
        float t = 0.0f;
#pragma unroll
        for (int i = 0; i < 8; i++) t += red[i];
        g_c = t;
    }
}

// alpha[l] = X[l].w1, beta[l] = X[l].w2  (exact fp32 inputs)
__global__ void __launch_bounds__(256) alphabeta_kernel(const float* __restrict__ X)
{
    __shared__ float reda[8], redb[8];
    const int l = blockIdx.x;
    float sa = 0.0f, sb = 0.0f;
    for (int e = threadIdx.x; e < EDIM; e += 256) {
        float x = X[(size_t)l * EDIM + e];
        sa += x * g_w1[e];
        sb += x * g_w2[e];
    }
#pragma unroll
    for (int m = 16; m >= 1; m >>= 1) {
        sa += __shfl_xor_sync(0xffffffffu, sa, m);
        sb += __shfl_xor_sync(0xffffffffu, sb, m);
    }
    if ((threadIdx.x & 31) == 0) { reda[threadIdx.x >> 5] = sa; redb[threadIdx.x >> 5] = sb; }
    __syncthreads();
    if (threadIdx.x == 0) {
        float ta = 0.0f, tb = 0.0f;
#pragma unroll
        for (int i = 0; i < 8; i++) { ta += reda[i]; tb += redb[i]; }
        g_alpha[l] = ta;
        g_beta[l]  = tb;
    }
}

// ---------------------------------------------------------------------------
// mgemm: Mt[e'][e] = sum_h Wk[h,e']*Wq[h,e]  (3-term).  grid (8, 8)
// ---------------------------------------------------------------------------
__global__ void __launch_bounds__(256, 2) mgemm_kernel()
{
    extern __shared__ char dynsm[];
    const int m0 = blockIdx.y * 128;   // e'
    const int n0 = blockIdx.x * 128;   // e

    float acc[4][4][4];
#pragma unroll
    for (int a = 0; a < 4; a++)
#pragma unroll
        for (int b = 0; b < 4; b++)
#pragma unroll
            for (int cc = 0; cc < 4; cc++) acc[a][b][cc] = 0.0f;

    run_tile3(g_WkThi, g_WkTlo, g_WqThi, g_WqTlo, m0, n0, HDIM, dynsm, acc);

    const int tid = threadIdx.x;
    const int wid = tid >> 5, lane = tid & 31;
    const int wm = wid >> 2, wn = wid & 3;

#pragma unroll
    for (int mi = 0; mi < 4; mi++) {
        const int r0 = m0 + wm * 64 + mi * 16 + (lane >> 2);
#pragma unroll
        for (int ni = 0; ni < 4; ni++) {
            const int gc = n0 + wn * 32 + ni * 8 + 2 * (lane & 3);
#pragma unroll
            for (int hh = 0; hh < 2; hh++) {
                const int rr = r0 + hh * 8;
                const float v0 = acc[mi][ni][2 * hh], v1 = acc[mi][ni][2 * hh + 1];
                __nv_bfloat162 h2, l2;
                h2.x = __float2bfloat16(v0);
                h2.y = __float2bfloat16(v1);
                l2.x = __float2bfloat16(v0 - __bfloat162float(h2.x));
                l2.y = __float2bfloat16(v1 - __bfloat162float(h2.y));
                *(__nv_bfloat162*)(g_Mhi + (size_t)rr * EDIM + gc) = h2;
                *(__nv_bfloat162*)(g_Mlo + (size_t)rr * EDIM + gc) = l2;
            }
        }
    }
}

// ---------------------------------------------------------------------------
// GEMM1: z=0: Qk = X*M^T (bf16 hi/lo + fp16 out);  z=1: V = X*Wv^T + bv
// grid (8, 128, 2)
// ---------------------------------------------------------------------------
__global__ void __launch_bounds__(256, 2) gemm1_kernel(const float* __restrict__ bv)
{
    extern __shared__ char dynsm[];
    const int z  = blockIdx.z;
    const int m0 = blockIdx.y * 128;
    const int n0 = blockIdx.x * 128;

    const __nv_bfloat16* Bh = z ? g_Wvhi : g_Mhi;
    const __nv_bfloat16* Bl = z ? g_Wvlo : g_Mlo;

    float acc[4][4][4];
#pragma unroll
    for (int a = 0; a < 4; a++)
#pragma unroll
        for (int b = 0; b < 4; b++)
#pragma unroll
            for (int cc = 0; cc < 4; cc++) acc[a][b][cc] = 0.0f;

    run_tile3(g_Xhi, g_Xlo, Bh, Bl, m0, n0, EDIM, dynsm, acc);

    const int tid = threadIdx.x;
    const int wid = tid >> 5, lane = tid & 31;
    const int wm = wid >> 2, wn = wid & 3;

#pragma unroll
    for (int mi = 0; mi < 4; mi++) {
        const int r0 = m0 + wm * 64 + mi * 16 + (lane >> 2);
#pragma unroll
        for (int ni = 0; ni < 4; ni++) {
            const int gc = n0 + wn * 32 + ni * 8 + 2 * (lane & 3);
            if (z == 1) {
                const float b0 = __ldg(&bv[gc]), b1 = __ldg(&bv[gc + 1]);
                *(float2*)(g_V + (size_t)r0 * HDIM + gc) =
                    make_float2(acc[mi][ni][0] + b0, acc[mi][ni][1] + b1);
                *(float2*)(g_V + (size_t)(r0 + 8) * HDIM + gc) =
                    make_float2(acc[mi][ni][2] + b0, acc[mi][ni][3] + b1);
            } else {
#pragma unroll
                for (int hh = 0; hh < 2; hh++) {
                    const int rr = r0 + hh * 8;
                    const float v0 = acc[mi][ni][2 * hh], v1 = acc[mi][ni][2 * hh + 1];
                    __nv_bfloat162 h2, l2;
                    h2.x = __float2bfloat16(v0);
                    h2.y = __float2bfloat16(v1);
                    l2.x = __float2bfloat16(v0 - __bfloat162float(h2.x));
                    l2.y = __float2bfloat16(v1 - __bfloat162float(h2.y));
                    *(__nv_bfloat162*)(g_Qkhi + (size_t)rr * EDIM + gc) = h2;
                    *(__nv_bfloat162*)(g_Qklo + (size_t)rr * EDIM + gc) = l2;
                    *(__half2*)(g_Qk16 + (size_t)rr * EDIM + gc) = __floats2half2_rn(v0, v1);
                }
            }
        }
    }
}

// ---------------------------------------------------------------------------
// Scores epilogue helper: exp + colsum (+ optional diag), with alpha/beta/c.
// ---------------------------------------------------------------------------
__device__ __forceinline__ void scores_epilogue(
    float (&acc)[4][4][4], int bz, int m0, int n0, bool diagblk)
{
    __shared__ float sred[128];
    const int tid = threadIdx.x;
    const int wid = tid >> 5, lane = tid & 31;
    const int wm = wid >> 2, wn = wid & 3;
    const float sc = 0.015625f;   // 1/sqrt(4096)
    const float cc = g_c;

    if (tid < 128) sred[tid] = 0.0f;

    float2 csum[4];
#pragma unroll
    for (int ni = 0; ni < 4; ni++) csum[ni] = make_float2(0.0f, 0.0f);

#pragma unroll
    for (int mi = 0; mi < 4; mi++) {
        const int lr = wm * 64 + mi * 16 + (lane >> 2);
        const float a0 = g_alpha[(size_t)bz * LSEQ + m0 + lr];
        const float a1 = g_alpha[(size_t)bz * LSEQ + m0 + lr + 8];
#pragma unroll
        for (int ni = 0; ni < 4; ni++) {
            const int lc = wn * 32 + ni * 8 + 2 * (lane & 3);
            const float b0 = g_beta[(size_t)bz * LSEQ + n0 + lc];
            const float b1 = g_beta[(size_t)bz * LSEQ + n0 + lc + 1];
            const float e00 = __expf((acc[mi][ni][0] + a0 + b0 + cc) * sc);
            const float e01 = __expf((acc[mi][ni][1] + a0 + b1 + cc) * sc);
            const float e10 = __expf((acc[mi][ni][2] + a1 + b0 + cc) * sc);
            const float e11 = __expf((acc[mi][ni][3] + a1 + b1 + cc) * sc);
            csum[ni].x += e00 + e10;
            csum[ni].y += e01 + e11;
            if (diagblk) {
                if (lr == lc)         g_diag[(size_t)bz * LSEQ + m0 + lr] = e00;
                if (lr == lc + 1)     g_diag[(size_t)bz * LSEQ + m0 + lr] = e01;
                if (lr + 8 == lc)     g_diag[(size_t)bz * LSEQ + m0 + lr + 8] = e10;
                if (lr + 8 == lc + 1) g_diag[(size_t)bz * LSEQ + m0 + lr + 8] = e11;
            }
        }
    }

    __syncthreads();   // sred init visible

#pragma unroll
    for (int ni = 0; ni < 4; ni++) {
#pragma unroll
        for (int m = 4; m <= 16; m <<= 1) {
            csum[ni].x += __shfl_xor_sync(0xffffffffu, csum[ni].x, m);
            csum[ni].y += __shfl_xor_sync(0xffffffffu, csum[ni].y, m);
        }
        if (lane < 4) {
            atomicAdd(&sred[wn * 32 + ni * 8 + 2 * lane],     csum[ni].x);
            atomicAdd(&sred[wn * 32 + ni * 8 + 2 * lane + 1], csum[ni].y);
        }
    }

    __syncthreads();
    if (tid < 128)
        atomicAdd(&g_colsum[(size_t)bz * LSEQ + n0 + tid], sred[tid]);
}

// ---------------------------------------------------------------------------
// GEMM2 off-diagonal: S = Qk16 * X16^T (fp16 in, fp16 acc).  grid (32, 32, NB)
// ---------------------------------------------------------------------------
__global__ void __launch_bounds__(256, 2) gemm2_off_kernel()
{
    if (blockIdx.x == blockIdx.y) return;   // diag handled separately
    extern __shared__ char dynsm[];

    const int bz = blockIdx.z;
    const int m0 = blockIdx.y * 128;
    const int n0 = blockIdx.x * 128;
    const size_t bo = (size_t)bz * LSEQ * EDIM;

    uint32_t acch[4][4][2];
#pragma unroll
    for (int a = 0; a < 4; a++)
#pragma unroll
        for (int b = 0; b < 4; b++) { acch[a][b][0] = 0; acch[a][b][1] = 0; }

    run_tile_h(g_Qk16 + bo, g_X16 + bo, m0, n0, EDIM, dynsm, acch);

    float acc[4][4][4];
#pragma unroll
    for (int a = 0; a < 4; a++)
#pragma unroll
        for (int b = 0; b < 4; b++) {
            const __half2 p0 = *reinterpret_cast<__half2*>(&acch[a][b][0]);
            const __half2 p1 = *reinterpret_cast<__half2*>(&acch[a][b][1]);
            acc[a][b][0] = __half2float(p0.x);
            acc[a][b][1] = __half2float(p0.y);
            acc[a][b][2] = __half2float(p1.x);
            acc[a][b][3] = __half2float(p1.y);
        }

    scores_epilogue(acc, bz, m0, n0, false);
}

// ---------------------------------------------------------------------------
// GEMM2 diagonal: 3-term bf16 split, diag extraction.  grid (32, NB)
// ---------------------------------------------------------------------------
__global__ void __launch_bounds__(256, 2) gemm2_diag_kernel()
{
    extern __shared__ char dynsm[];
    const int bz = blockIdx.y;
    const int m0 = blockIdx.x * 128;
    const size_t bo = (size_t)bz * LSEQ * EDIM;

    float acc[4][4][4];
#pragma unroll
    for (int a = 0; a < 4; a++)
#pragma unroll
        for (int b = 0; b < 4; b++)
#pragma unroll
            for (int cc = 0; cc < 4; cc++) acc[a][b][cc] = 0.0f;

    run_tile3(g_Qkhi + bo, g_Qklo + bo, g_Xhi + bo, g_Xlo + bo,
              m0, m0, EDIM, dynsm, acc);
    scores_epilogue(acc, bz, m0, m0, true);
}

// ---------------------------------------------------------------------------
__global__ void __launch_bounds__(256) finalize_kernel(float* __restrict__ out)
{
    const int row = blockIdx.x;
    const float scale = g_diag[row] / g_colsum[row];
    const float4* v = (const float4*)(g_V + (size_t)row * HDIM);
    float4* o = (float4*)(out + (size_t)row * HDIM);
    float4 x = v[threadIdx.x];
    x.x *= scale; x.y *= scale; x.z *= scale; x.w *= scale;
    o[threadIdx.x] = x;
}

__global__ void zero_kernel()
{
    const int i = blockIdx.x * 256 + threadIdx.x;
    if (i < ML) g_colsum[i] = 0.0f;
}

// ---------------------------------------------------------------------------
extern "C" void kernel_launch(void* const* d_in, const int* in_sizes, int n_in,
                              void* d_out, int out_size)
{
    (void)in_sizes; (void)n_in; (void)out_size;
    const float* X  = (const float*)d_in[0];
    const float* Wq = (const float*)d_in[1];
    const float* bq = (const float*)d_in[2];
    const float* Wk = (const float*)d_in[3];
    const float* bk = (const float*)d_in[4];
    const float* Wv = (const float*)d_in[5];
    const float* bv = (const float*)d_in[6];
    float* out = (float*)d_out;

    // Idempotent host-side attribute setup (capture-safe, not stream ops).
    cudaFuncSetAttribute(mgemm_kernel,      cudaFuncAttributeMaxDynamicSharedMemorySize, DYNSMEM);
    cudaFuncSetAttribute(gemm1_kernel,      cudaFuncAttributeMaxDynamicSharedMemorySize, DYNSMEM);
    cudaFuncSetAttribute(gemm2_off_kernel,  cudaFuncAttributeMaxDynamicSharedMemorySize, DYNSMEM);
    cudaFuncSetAttribute(gemm2_diag_kernel, cudaFuncAttributeMaxDynamicSharedMemorySize, DYNSMEM);
    cudaFuncSetAttribute(mgemm_kernel,      cudaFuncAttributePreferredSharedMemoryCarveout, 100);
    cudaFuncSetAttribute(gemm1_kernel,      cudaFuncAttributePreferredSharedMemoryCarveout, 100);
    cudaFuncSetAttribute(gemm2_off_kernel,  cudaFuncAttributePreferredSharedMemoryCarveout, 100);
    cudaFuncSetAttribute(gemm2_diag_kernel, cudaFuncAttributePreferredSharedMemoryCarveout, 100);

    zero_kernel<<<(ML + 255) / 256, 256>>>();

    convx_kernel<<<(ML * EDIM / 4) / 256, 256>>>(X);
    convv_kernel<<<(HDIM * EDIM / 4) / 256, 256>>>(Wv);

    dim3 gt(EDIM / 32, HDIM / 32, 2);
    transw_kernel<<<gt, 256>>>(Wq, Wk);

    dim3 gb(EDIM, 2);
    biasw_kernel<<<gb, 256>>>(bq, bk);
    cscalar_kernel<<<1, 256>>>(bq, bk);

    dim3 gm(EDIM / 128, EDIM / 128);
    mgemm_kernel<<<gm, 256, DYNSMEM>>>();

    alphabeta_kernel<<<ML, 256>>>(X);

    dim3 g1(EDIM / 128, ML / 128, 2);
    gemm1_kernel<<<g1, 256, DYNSMEM>>>(bv);

    dim3 g2(LSEQ / 128, LSEQ / 128, NB);
    gemm2_off_kernel<<<g2, 256, DYNSMEM>>>();

    dim3 g2d(LSEQ / 128, NB);
    gemm2_diag_kernel<<<g2d, 256, DYNSMEM>>>();

    finalize_kernel<<<ML, 256>>>(out);
}

// round 14
// speedup vs baseline: 1.6225x; 1.1769x over previous
#include <cuda_runtime.h>
#include <cuda_bf16.h>
#include <cuda_fp16.h>
#include <math.h>
#include <stdint.h>

#define NB   4
#define LSEQ 4096
#define EDIM 1024
#define HDIM 1024
#define ML   (NB * LSEQ)      // 16384

// ---------------- scratch (static device arrays; no allocation APIs) -------
__device__ __nv_bfloat16 g_Xhi[ML * EDIM];          // 32 MB
__device__ __nv_bfloat16 g_Xlo[ML * EDIM];
__device__ __half        g_X16[ML * EDIM];          // 32 MB fp16 copy of X
__device__ __half        g_Qk16[ML * EDIM];         // 32 MB fp16 copy of Qk
__device__ __half        g_Wv16[HDIM * EDIM];       // 2 MB fp16 copy of Wv
__device__ __nv_bfloat16 g_WqThi[EDIM * HDIM];      // Wq^T: [e][h]
__device__ __nv_bfloat16 g_WqTlo[EDIM * HDIM];
__device__ __nv_bfloat16 g_WkThi[EDIM * HDIM];
__device__ __nv_bfloat16 g_WkTlo[EDIM * HDIM];
__device__ __nv_bfloat16 g_Mhi[EDIM * EDIM];        // M^T stored [e'][e]
__device__ __nv_bfloat16 g_Mlo[EDIM * EDIM];
__device__ __nv_bfloat16 g_Qkhi[ML * EDIM];         // Qk = X*M^T
__device__ __nv_bfloat16 g_Qklo[ML * EDIM];
__device__ float         g_V[ML * HDIM];            // 64 MB
__device__ float         g_w1[EDIM];                // Wq^T * bk
__device__ float         g_w2[EDIM];                // Wk^T * bq
__device__ float         g_alpha[ML];               // X * w1
__device__ float         g_beta[ML];                // X * w2
__device__ float         g_c;                       // bq . bk
__device__ float         g_colsum[ML];
__device__ float         g_diag[ML];

// ---------------- helpers --------------------------------------------------
__device__ __forceinline__ uint32_t smem_u32(const void* p) {
    uint32_t a;
    asm("{ .reg .u64 t; cvta.to.shared.u64 t, %1; cvt.u32.u64 %0, t; }"
        : "=r"(a) : "l"(p));
    return a;
}

__device__ __forceinline__ void cp16(uint32_t s, const void* g) {
    asm volatile("cp.async.cg.shared.global [%0], [%1], 16;" :: "r"(s), "l"(g));
}
#define CP_COMMIT() asm volatile("cp.async.commit_group;" ::: "memory")
#define CP_WAIT2()  asm volatile("cp.async.wait_group 2;" ::: "memory")
#define CP_WAIT1()  asm volatile("cp.async.wait_group 1;" ::: "memory")
#define CP_WAIT0()  asm volatile("cp.async.wait_group 0;" ::: "memory")

__device__ __forceinline__ void ldsm4(uint32_t* a, uint32_t addr) {
    asm volatile("ldmatrix.sync.aligned.m8n8.x4.shared.b16 {%0,%1,%2,%3}, [%4];"
                 : "=r"(a[0]), "=r"(a[1]), "=r"(a[2]), "=r"(a[3]) : "r"(addr));
}
__device__ __forceinline__ void ldsm2(uint32_t* b, uint32_t addr) {
    asm volatile("ldmatrix.sync.aligned.m8n8.x2.shared.b16 {%0,%1}, [%2];"
                 : "=r"(b[0]), "=r"(b[1]) : "r"(addr));
}
__device__ __forceinline__ void mma16816(float* d, const uint32_t* a, const uint32_t* b) {
    asm volatile(
        "mma.sync.aligned.m16n8k16.row.col.f32.bf16.bf16.f32 "
        "{%0,%1,%2,%3}, {%4,%5,%6,%7}, {%8,%9}, {%0,%1,%2,%3};"
        : "+f"(d[0]), "+f"(d[1]), "+f"(d[2]), "+f"(d[3])
        : "r"(a[0]), "r"(a[1]), "r"(a[2]), "r"(a[3]), "r"(b[0]), "r"(b[1]));
}
// fp16 inputs, fp16 accumulate (off-diag scores)
__device__ __forceinline__ void mma16816h(uint32_t* d, const uint32_t* a, const uint32_t* b) {
    asm volatile(
        "mma.sync.aligned.m16n8k16.row.col.f16.f16.f16.f16 "
        "{%0,%1}, {%2,%3,%4,%5}, {%6,%7}, {%0,%1};"
        : "+r"(d[0]), "+r"(d[1])
        : "r"(a[0]), "r"(a[1]), "r"(a[2]), "r"(a[3]), "r"(b[0]), "r"(b[1]));
}
// fp16 inputs, f32 accumulate (V projection)
__device__ __forceinline__ void mma16816hf(float* d, const uint32_t* a, const uint32_t* b) {
    asm volatile(
        "mma.sync.aligned.m16n8k16.row.col.f32.f16.f16.f32 "
        "{%0,%1,%2,%3}, {%4,%5,%6,%7}, {%8,%9}, {%0,%1,%2,%3};"
        : "+f"(d[0]), "+f"(d[1]), "+f"(d[2]), "+f"(d[3])
        : "r"(a[0]), "r"(a[1]), "r"(a[2]), "r"(a[3]), "r"(b[0]), "r"(b[1]));
}

// ---------------- tiling constants -----------------------------------------
#define PITCH   80                    // bytes per smem row (32 halves + 16B pad)
#define TSZ     (128 * PITCH)         // one operand tile: 10240 B
#define STG3    (4 * TSZ)             // 3-term stage: Ah, Al, Bh, Bl = 40960 B
#define STG1    (2 * TSZ)             // 1-term stage: A, B = 20480 B
#define DYNSMEM (2 * STG3)            // 81920 B (== 4 * STG1)

// ---------------------------------------------------------------------------
// run_tile3: 128x128 tile, split-bf16, 2-stage pipe, term-outer mma order.
// ---------------------------------------------------------------------------
__device__ __forceinline__ void run_tile3(
    const __nv_bfloat16* __restrict__ Ah, const __nv_bfloat16* __restrict__ Al,
    const __nv_bfloat16* __restrict__ Bh, const __nv_bfloat16* __restrict__ Bl,
    int m0, int n0, int Kdim, char* sm, float (&acc)[4][4][4])
{
    const int tid  = threadIdx.x;
    const int wid  = tid >> 5, lane = tid & 31;
    const int wm   = wid >> 2, wn = wid & 3;
    const uint32_t sbase = smem_u32(sm);

    const int r  = tid >> 1, cg = tid & 1;
    const size_t ga = (size_t)(m0 + r) * Kdim + cg * 16;
    const size_t gb = (size_t)(n0 + r) * Kdim + cg * 16;
    const uint32_t soff = (uint32_t)(r * PITCH + cg * 32);

    const uint32_t aoff = (uint32_t)((wm * 64 + (lane & 15)) * PITCH + (lane >> 4) * 16);
    const uint32_t boff = (uint32_t)((wn * 32 + (lane & 7)) * PITCH + ((lane >> 3) & 1) * 16);

#define LOADC3(st, kc) do {                                                   \
    const uint32_t s0 = sbase + (uint32_t)(st) * STG3 + soff;                 \
    cp16(s0 + 0 * TSZ,      Ah + ga + (kc));                                  \
    cp16(s0 + 0 * TSZ + 16, Ah + ga + (kc) + 8);                              \
    cp16(s0 + 1 * TSZ,      Al + ga + (kc));                                  \
    cp16(s0 + 1 * TSZ + 16, Al + ga + (kc) + 8);                              \
    cp16(s0 + 2 * TSZ,      Bh + gb + (kc));                                  \
    cp16(s0 + 2 * TSZ + 16, Bh + gb + (kc) + 8);                              \
    cp16(s0 + 3 * TSZ,      Bl + gb + (kc));                                  \
    cp16(s0 + 3 * TSZ + 16, Bl + gb + (kc) + 8);                              \
    CP_COMMIT();                                                              \
} while (0)

    const int NC = Kdim / 32;
    LOADC3(0, 0);

#pragma unroll 1
    for (int c = 0; c < NC; c++) {
        if (c + 1 < NC) { LOADC3((c + 1) & 1, (c + 1) * 32); CP_WAIT1(); }
        else            { CP_WAIT0(); }
        __syncthreads();

        const uint32_t tb = sbase + (uint32_t)(c & 1) * STG3;
#pragma unroll
        for (int k16 = 0; k16 < 2; k16++) {
            uint32_t ah[4][4], al[4][4], bh[4][2], bl[4][2];
#pragma unroll
            for (int mi = 0; mi < 4; mi++) {
                ldsm4(ah[mi], tb + 0 * TSZ + aoff + mi * 16 * PITCH + k16 * 32);
                ldsm4(al[mi], tb + 1 * TSZ + aoff + mi * 16 * PITCH + k16 * 32);
            }
#pragma unroll
            for (int ni = 0; ni < 4; ni++) {
                ldsm2(bh[ni], tb + 2 * TSZ + boff + ni * 8 * PITCH + k16 * 32);
                ldsm2(bl[ni], tb + 3 * TSZ + boff + ni * 8 * PITCH + k16 * 32);
            }
#pragma unroll
            for (int mi = 0; mi < 4; mi++)
#pragma unroll
                for (int ni = 0; ni < 4; ni++)
                    mma16816(acc[mi][ni], ah[mi], bh[ni]);
#pragma unroll
            for (int mi = 0; mi < 4; mi++)
#pragma unroll
                for (int ni = 0; ni < 4; ni++)
                    mma16816(acc[mi][ni], ah[mi], bl[ni]);
#pragma unroll
            for (int mi = 0; mi < 4; mi++)
#pragma unroll
                for (int ni = 0; ni < 4; ni++)
                    mma16816(acc[mi][ni], al[mi], bh[ni]);
        }
        __syncthreads();
    }
#undef LOADC3
}

// ---------------------------------------------------------------------------
// run_tile_h: 128x128 tile, fp16 in / fp16 acc, 4-stage pipe, 1 sync/chunk.
// ---------------------------------------------------------------------------
__device__ __forceinline__ void run_tile_h(
    const __half* __restrict__ A, const __half* __restrict__ B,
    int m0, int n0, int Kdim, char* sm, uint32_t (&acc)[4][4][2])
{
    const int tid  = threadIdx.x;
    const int wid  = tid >> 5, lane = tid & 31;
    const int wm   = wid >> 2, wn = wid & 3;
    const uint32_t sbase = smem_u32(sm);

    const int r  = tid >> 1, cg = tid & 1;
    const size_t ga = (size_t)(m0 + r) * Kdim + cg * 16;
    const size_t gb = (size_t)(n0 + r) * Kdim + cg * 16;
    const uint32_t soff = (uint32_t)(r * PITCH + cg * 32);

    const uint32_t aoff = (uint32_t)((wm * 64 + (lane & 15)) * PITCH + (lane >> 4) * 16);
    const uint32_t boff = (uint32_t)((wn * 32 + (lane & 7)) * PITCH + ((lane >> 3) & 1) * 16);

#define LOADCH(st, kc) do {                                                   \
    const uint32_t s0 = sbase + (uint32_t)(st) * STG1 + soff;                 \
    cp16(s0,            A + ga + (kc));                                       \
    cp16(s0 + 16,       A + ga + (kc) + 8);                                   \
    cp16(s0 + TSZ,      B + gb + (kc));                                       \
    cp16(s0 + TSZ + 16, B + gb + (kc) + 8);                                   \
    CP_COMMIT();                                                              \
} while (0)

    const int NC = Kdim / 32;
    LOADCH(0, 0);
    LOADCH(1, 32);
    LOADCH(2, 64);

#pragma unroll 1
    for (int c = 0; c < NC; c++) {
        CP_WAIT2();
        __syncthreads();
        const uint32_t tb = sbase + (uint32_t)(c & 3) * STG1;
#pragma unroll
        for (int k16 = 0; k16 < 2; k16++) {
            uint32_t ah[4][4], bh[4][2];
#pragma unroll
            for (int mi = 0; mi < 4; mi++)
                ldsm4(ah[mi], tb + aoff + mi * 16 * PITCH + k16 * 32);
#pragma unroll
            for (int ni = 0; ni < 4; ni++)
                ldsm2(bh[ni], tb + TSZ + boff + ni * 8 * PITCH + k16 * 32);
#pragma unroll
            for (int mi = 0; mi < 4; mi++)
#pragma unroll
                for (int ni = 0; ni < 4; ni++)
                    mma16816h(acc[mi][ni], ah[mi], bh[ni]);
        }
        if (c + 3 < NC) LOADCH((c + 3) & 3, (c + 3) * 32);
    }
#undef LOADCH
}

// ---------------------------------------------------------------------------
// run_tile_h32: fp16 in / f32 acc, 4-stage pipe (V projection).
// ---------------------------------------------------------------------------
__device__ __forceinline__ void run_tile_h32(
    const __half* __restrict__ A, const __half* __restrict__ B,
    int m0, int n0, int Kdim, char* sm, float (&acc)[4][4][4])
{
    const int tid  = threadIdx.x;
    const int wid  = tid >> 5, lane = tid & 31;
    const int wm   = wid >> 2, wn = wid & 3;
    const uint32_t sbase = smem_u32(sm);

    const int r  = tid >> 1, cg = tid & 1;
    const size_t ga = (size_t)(m0 + r) * Kdim + cg * 16;
    const size_t gb = (size_t)(n0 + r) * Kdim + cg * 16;
    const uint32_t soff = (uint32_t)(r * PITCH + cg * 32);

    const uint32_t aoff = (uint32_t)((wm * 64 + (lane & 15)) * PITCH + (lane >> 4) * 16);
    const uint32_t boff = (uint32_t)((wn * 32 + (lane & 7)) * PITCH + ((lane >> 3) & 1) * 16);

#define LOADCF(st, kc) do {                                                   \
    const uint32_t s0 = sbase + (uint32_t)(st) * STG1 + soff;                 \
    cp16(s0,            A + ga + (kc));                                       \
    cp16(s0 + 16,       A + ga + (kc) + 8);                                   \
    cp16(s0 + TSZ,      B + gb + (kc));                                       \
    cp16(s0 + TSZ + 16, B + gb + (kc) + 8);                                   \
    CP_COMMIT();                                                              \
} while (0)

    const int NC = Kdim / 32;
    LOADCF(0, 0);
    LOADCF(1, 32);
    LOADCF(2, 64);

#pragma unroll 1
    for (int c = 0; c < NC; c++) {
        CP_WAIT2();
        __syncthreads();
        const uint32_t tb = sbase + (uint32_t)(c & 3) * STG1;
#pragma unroll
        for (int k16 = 0; k16 < 2; k16++) {
            uint32_t ah[4][4], bh[4][2];
#pragma unroll
            for (int mi = 0; mi < 4; mi++)
                ldsm4(ah[mi], tb + aoff + mi * 16 * PITCH + k16 * 32);
#pragma unroll
            for (int ni = 0; ni < 4; ni++)
                ldsm2(bh[ni], tb + TSZ + boff + ni * 8 * PITCH + k16 * 32);
#pragma unroll
            for (int mi = 0; mi < 4; mi++)
#pragma unroll
                for (int ni = 0; ni < 4; ni++)
                    mma16816hf(acc[mi][ni], ah[mi], bh[ni]);
        }
        if (c + 3 < NC) LOADCF((c + 3) & 3, (c + 3) * 32);
    }
#undef LOADCF
}

// ---------------------------------------------------------------------------
// Conversions / transposes
// ---------------------------------------------------------------------------
__device__ __forceinline__ void split4(float4 v, __nv_bfloat162& h0, __nv_bfloat162& h1,
                                       __nv_bfloat162& l0, __nv_bfloat162& l1) {
    float f[4] = {v.x, v.y, v.z, v.w};
    __nv_bfloat16 h[4], l[4];
#pragma unroll
    for (int i = 0; i < 4; i++) {
        h[i] = __float2bfloat16(f[i]);
        l[i] = __float2bfloat16(f[i] - __bfloat162float(h[i]));
    }
    h0.x = h[0]; h0.y = h[1]; h1.x = h[2]; h1.y = h[3];
    l0.x = l[0]; l0.y = l[1]; l1.x = l[2]; l1.y = l[3];
}

__global__ void __launch_bounds__(256) convx_kernel(const float* __restrict__ X) {
    const size_t i = (size_t)blockIdx.x * 256 + threadIdx.x;
    float4 v = ((const float4*)X)[i];
    __nv_bfloat162 h0, h1, l0, l1;
    split4(v, h0, h1, l0, l1);
    ((__nv_bfloat162*)g_Xhi)[2 * i]     = h0;
    ((__nv_bfloat162*)g_Xhi)[2 * i + 1] = h1;
    ((__nv_bfloat162*)g_Xlo)[2 * i]     = l0;
    ((__nv_bfloat162*)g_Xlo)[2 * i + 1] = l1;
    ((__half2*)g_X16)[2 * i]     = __floats2half2_rn(v.x, v.y);
    ((__half2*)g_X16)[2 * i + 1] = __floats2half2_rn(v.z, v.w);
}

__global__ void __launch_bounds__(256) convv_kernel(const float* __restrict__ Wv) {
    const size_t i = (size_t)blockIdx.x * 256 + threadIdx.x;
    float4 v = ((const float4*)Wv)[i];
    ((__half2*)g_Wv16)[2 * i]     = __floats2half2_rn(v.x, v.y);
    ((__half2*)g_Wv16)[2 * i + 1] = __floats2half2_rn(v.z, v.w);
}

// Transposed split copies of Wq, Wk: WT[e][h] = W[h][e], bf16 hi/lo.
__global__ void __launch_bounds__(256) transw_kernel(
    const float* __restrict__ Wq, const float* __restrict__ Wk)
{
    __shared__ float t[32][33];
    const int z = blockIdx.z;
    const float* W = z ? Wk : Wq;
    __nv_bfloat16* Th = z ? g_WkThi : g_WqThi;
    __nv_bfloat16* Tl = z ? g_WkTlo : g_WqTlo;
    const int e0 = blockIdx.x * 32, h0 = blockIdx.y * 32;
    const int tx = threadIdx.x & 31, ty = threadIdx.x >> 5;  // 32 x 8

#pragma unroll
    for (int i = ty; i < 32; i += 8)
        t[i][tx] = W[(size_t)(h0 + i) * EDIM + e0 + tx];
    __syncthreads();
#pragma unroll
    for (int i = ty; i < 32; i += 8) {
        float v = t[tx][i];                 // = W[h0+tx][e0+i]
        __nv_bfloat16 h = __float2bfloat16(v);
        __nv_bfloat16 l = __float2bfloat16(v - __bfloat162float(h));
        Th[(size_t)(e0 + i) * HDIM + h0 + tx] = h;
        Tl[(size_t)(e0 + i) * HDIM + h0 + tx] = l;
    }
}

// w1[e] = sum_h Wq[h,e]*bk[h],  w2[e] = sum_h Wk[h,e]*bq[h]
__global__ void __launch_bounds__(256) biasw_kernel(
    const float* __restrict__ bq, const float* __restrict__ bk)
{
    __shared__ float red[8];
    const int e = blockIdx.x, z = blockIdx.y;
    const __nv_bfloat16* Th = z ? g_WkThi : g_WqThi;
    const __nv_bfloat16* Tl = z ? g_WkTlo : g_WqTlo;
    const float* b = z ? bq : bk;
    float s = 0.0f;
    for (int h = threadIdx.x; h < HDIM; h += 256)
        s += (__bfloat162float(Th[(size_t)e * HDIM + h]) +
              __bfloat162float(Tl[(size_t)e * HDIM + h])) * b[h];
#pragma unroll
    for (int m = 16; m >= 1; m >>= 1) s += __shfl_xor_sync(0xffffffffu, s, m);
    if ((threadIdx.x & 31) == 0) red[threadIdx.x >> 5] = s;
    __syncthreads();
    if (threadIdx.x == 0) {
        float t = 0.0f;
#pragma unroll
        for (int i = 0; i < 8; i++) t += red[i];
        (z ? g_w2 : g_w1)[e] = t;
    }
}

__global__ void cscalar_kernel(const float* __restrict__ bq,
                               const float* __restrict__ bk)
{
    __shared__ float red[8];
    float s = 0.0f;
    for (int h = threadIdx.x; h < HDIM; h += 256) s += bq[h] * bk[h];
#pragma unroll
    for (int m = 16; m >= 1; m >>= 1) s += __shfl_xor_sync(0xffffffffu, s, m);
    if ((threadIdx.x & 31) == 0) red[threadIdx.x >> 5] = s;
    __syncthreads();
    if (threadIdx.x == 0) {
        float t = 0.0f;
#pragma unroll
        for (int i = 0; i < 8; i++) t += red[i];
        g_c = t;
    }
}

// alpha[l] = X[l].w1, beta[l] = X[l].w2  (exact fp32 inputs)
__global__ void __launch_bounds__(256) alphabeta_kernel(const float* __restrict__ X)
{
    __shared__ float reda[8], redb[8];
    const int l = blockIdx.x;
    float sa = 0.0f, sb = 0.0f;
    for (int e = threadIdx.x; e < EDIM; e += 256) {
        float x = X[(size_t)l * EDIM + e];
        sa += x * g_w1[e];
        sb += x * g_w2[e];
    }
#pragma unroll
    for (int m = 16; m >= 1; m >>= 1) {
        sa += __shfl_xor_sync(0xffffffffu, sa, m);
        sb += __shfl_xor_sync(0xffffffffu, sb, m);
    }
    if ((threadIdx.x & 31) == 0) { reda[threadIdx.x >> 5] = sa; redb[threadIdx.x >> 5] = sb; }
    __syncthreads();
    if (threadIdx.x == 0) {
        float ta = 0.0f, tb = 0.0f;
#pragma unroll
        for (int i = 0; i < 8; i++) { ta += reda[i]; tb += redb[i]; }
        g_alpha[l] = ta;
        g_beta[l]  = tb;
    }
}

// ---------------------------------------------------------------------------
// mgemm: Mt[e'][e] = sum_h Wk[h,e']*Wq[h,e]  (3-term).  grid (8, 8)
// ---------------------------------------------------------------------------
__global__ void __launch_bounds__(256, 2) mgemm_kernel()
{
    extern __shared__ char dynsm[];
    const int m0 = blockIdx.y * 128;   // e'
    const int n0 = blockIdx.x * 128;   // e

    float acc[4][4][4];
#pragma unroll
    for (int a = 0; a < 4; a++)
#pragma unroll
        for (int b = 0; b < 4; b++)
#pragma unroll
            for (int cc = 0; cc < 4; cc++) acc[a][b][cc] = 0.0f;

    run_tile3(g_WkThi, g_WkTlo, g_WqThi, g_WqTlo, m0, n0, HDIM, dynsm, acc);

    const int tid = threadIdx.x;
    const int wid = tid >> 5, lane = tid & 31;
    const int wm = wid >> 2, wn = wid & 3;

#pragma unroll
    for (int mi = 0; mi < 4; mi++) {
        const int r0 = m0 + wm * 64 + mi * 16 + (lane >> 2);
#pragma unroll
        for (int ni = 0; ni < 4; ni++) {
            const int gc = n0 + wn * 32 + ni * 8 + 2 * (lane & 3);
#pragma unroll
            for (int hh = 0; hh < 2; hh++) {
                const int rr = r0 + hh * 8;
                const float v0 = acc[mi][ni][2 * hh], v1 = acc[mi][ni][2 * hh + 1];
                __nv_bfloat162 h2, l2;
                h2.x = __float2bfloat16(v0);
                h2.y = __float2bfloat16(v1);
                l2.x = __float2bfloat16(v0 - __bfloat162float(h2.x));
                l2.y = __float2bfloat16(v1 - __bfloat162float(h2.y));
                *(__nv_bfloat162*)(g_Mhi + (size_t)rr * EDIM + gc) = h2;
                *(__nv_bfloat162*)(g_Mlo + (size_t)rr * EDIM + gc) = l2;
            }
        }
    }
}

// ---------------------------------------------------------------------------
// GEMM1: z=0: Qk = X*M^T (3-term bf16; bf16 hi/lo + fp16 out)
//        z=1: V = X16*Wv16^T + bv (1-term fp16, f32 acc)
// grid (8, 128, 2)
// ---------------------------------------------------------------------------
__global__ void __launch_bounds__(256, 2) gemm1_kernel(const float* __restrict__ bv)
{
    extern __shared__ char dynsm[];
    const int z  = blockIdx.z;
    const int m0 = blockIdx.y * 128;
    const int n0 = blockIdx.x * 128;

    float acc[4][4][4];
#pragma unroll
    for (int a = 0; a < 4; a++)
#pragma unroll
        for (int b = 0; b < 4; b++)
#pragma unroll
            for (int cc = 0; cc < 4; cc++) acc[a][b][cc] = 0.0f;

    if (z == 1)
        run_tile_h32(g_X16, g_Wv16, m0, n0, EDIM, dynsm, acc);
    else
        run_tile3(g_Xhi, g_Xlo, g_Mhi, g_Mlo, m0, n0, EDIM, dynsm, acc);

    const int tid = threadIdx.x;
    const int wid = tid >> 5, lane = tid & 31;
    const int wm = wid >> 2, wn = wid & 3;

#pragma unroll
    for (int mi = 0; mi < 4; mi++) {
        const int r0 = m0 + wm * 64 + mi * 16 + (lane >> 2);
#pragma unroll
        for (int ni = 0; ni < 4; ni++) {
            const int gc = n0 + wn * 32 + ni * 8 + 2 * (lane & 3);
            if (z == 1) {
                const float b0 = __ldg(&bv[gc]), b1 = __ldg(&bv[gc + 1]);
                *(float2*)(g_V + (size_t)r0 * HDIM + gc) =
                    make_float2(acc[mi][ni][0] + b0, acc[mi][ni][1] + b1);
                *(float2*)(g_V + (size_t)(r0 + 8) * HDIM + gc) =
                    make_float2(acc[mi][ni][2] + b0, acc[mi][ni][3] + b1);
            } else {
#pragma unroll
                for (int hh = 0; hh < 2; hh++) {
                    const int rr = r0 + hh * 8;
                    const float v0 = acc[mi][ni][2 * hh], v1 = acc[mi][ni][2 * hh + 1];
                    __nv_bfloat162 h2, l2;
                    h2.x = __float2bfloat16(v0);
                    h2.y = __float2bfloat16(v1);
                    l2.x = __float2bfloat16(v0 - __bfloat162float(h2.x));
                    l2.y = __float2bfloat16(v1 - __bfloat162float(h2.y));
                    *(__nv_bfloat162*)(g_Qkhi + (size_t)rr * EDIM + gc) = h2;
                    *(__nv_bfloat162*)(g_Qklo + (size_t)rr * EDIM + gc) = l2;
                    *(__half2*)(g_Qk16 + (size_t)rr * EDIM + gc) = __floats2half2_rn(v0, v1);
                }
            }
        }
    }
}

// ---------------------------------------------------------------------------
// Scores epilogue helper: exp + colsum (+ optional diag), with alpha/beta/c.
// ---------------------------------------------------------------------------
__device__ __forceinline__ void scores_epilogue(
    float (&acc)[4][4][4], int bz, int m0, int n0, bool diagblk)
{
    __shared__ float sred[128];
    const int tid = threadIdx.x;
    const int wid = tid >> 5, lane = tid & 31;
    const int wm = wid >> 2, wn = wid & 3;
    const float sc = 0.015625f;   // 1/sqrt(4096)
    const float cc = g_c;

    if (tid < 128) sred[tid] = 0.0f;

    float2 csum[4];
#pragma unroll
    for (int ni = 0; ni < 4; ni++) csum[ni] = make_float2(0.0f, 0.0f);

#pragma unroll
    for (int mi = 0; mi < 4; mi++) {
        const int lr = wm * 64 + mi * 16 + (lane >> 2);
        const float a0 = g_alpha[(size_t)bz * LSEQ + m0 + lr];
        const float a1 = g_alpha[(size_t)bz * LSEQ + m0 + lr + 8];
#pragma unroll
        for (int ni = 0; ni < 4; ni++) {
            const int lc = wn * 32 + ni * 8 + 2 * (lane & 3);
            const float b0 = g_beta[(size_t)bz * LSEQ + n0 + lc];
            const float b1 = g_beta[(size_t)bz * LSEQ + n0 + lc + 1];
            const float e00 = __expf((acc[mi][ni][0] + a0 + b0 + cc) * sc);
            const float e01 = __expf((acc[mi][ni][1] + a0 + b1 + cc) * sc);
            const float e10 = __expf((acc[mi][ni][2] + a1 + b0 + cc) * sc);
            const float e11 = __expf((acc[mi][ni][3] + a1 + b1 + cc) * sc);
            csum[ni].x += e00 + e10;
            csum[ni].y += e01 + e11;
            if (diagblk) {
                if (lr == lc)         g_diag[(size_t)bz * LSEQ + m0 + lr] = e00;
                if (lr == lc + 1)     g_diag[(size_t)bz * LSEQ + m0 + lr] = e01;
                if (lr + 8 == lc)     g_diag[(size_t)bz * LSEQ + m0 + lr + 8] = e10;
                if (lr + 8 == lc + 1) g_diag[(size_t)bz * LSEQ + m0 + lr + 8] = e11;
            }
        }
    }

    __syncthreads();   // sred init visible

#pragma unroll
    for (int ni = 0; ni < 4; ni++) {
#pragma unroll
        for (int m = 4; m <= 16; m <<= 1) {
            csum[ni].x += __shfl_xor_sync(0xffffffffu, csum[ni].x, m);
            csum[ni].y += __shfl_xor_sync(0xffffffffu, csum[ni].y, m);
        }
        if (lane < 4) {
            atomicAdd(&sred[wn * 32 + ni * 8 + 2 * lane],     csum[ni].x);
            atomicAdd(&sred[wn * 32 + ni * 8 + 2 * lane + 1], csum[ni].y);
        }
    }

    __syncthreads();
    if (tid < 128)
        atomicAdd(&g_colsum[(size_t)bz * LSEQ + n0 + tid], sred[tid]);
}

// ---------------------------------------------------------------------------
// GEMM2 off-diagonal: S = Qk16 * X16^T (fp16 in, fp16 acc).  grid (32, 32, NB)
// ---------------------------------------------------------------------------
__global__ void __launch_bounds__(256, 2) gemm2_off_kernel()
{
    if (blockIdx.x == blockIdx.y) return;   // diag handled separately
    extern __shared__ char dynsm[];

    const int bz = blockIdx.z;
    const int m0 = blockIdx.y * 128;
    const int n0 = blockIdx.x * 128;
    const size_t bo = (size_t)bz * LSEQ * EDIM;

    uint32_t acch[4][4][2];
#pragma unroll
    for (int a = 0; a < 4; a++)
#pragma unroll
        for (int b = 0; b < 4; b++) { acch[a][b][0] = 0; acch[a][b][1] = 0; }

    run_tile_h(g_Qk16 + bo, g_X16 + bo, m0, n0, EDIM, dynsm, acch);

    float acc[4][4][4];
#pragma unroll
    for (int a = 0; a < 4; a++)
#pragma unroll
        for (int b = 0; b < 4; b++) {
            const __half2 p0 = *reinterpret_cast<__half2*>(&acch[a][b][0]);
            const __half2 p1 = *reinterpret_cast<__half2*>(&acch[a][b][1]);
            acc[a][b][0] = __half2float(p0.x);
            acc[a][b][1] = __half2float(p0.y);
            acc[a][b][2] = __half2float(p1.x);
            acc[a][b][3] = __half2float(p1.y);
        }

    scores_epilogue(acc, bz, m0, n0, false);
}

// ---------------------------------------------------------------------------
// GEMM2 diagonal: 3-term bf16 split, diag extraction.  grid (32, NB)
// ---------------------------------------------------------------------------
__global__ void __launch_bounds__(256, 2) gemm2_diag_kernel()
{
    extern __shared__ char dynsm[];
    const int bz = blockIdx.y;
    const int m0 = blockIdx.x * 128;
    const size_t bo = (size_t)bz * LSEQ * EDIM;

    float acc[4][4][4];
#pragma unroll
    for (int a = 0; a < 4; a++)
#pragma unroll
        for (int b = 0; b < 4; b++)
#pragma unroll
            for (int cc = 0; cc < 4; cc++) acc[a][b][cc] = 0.0f;

    run_tile3(g_Qkhi + bo, g_Qklo + bo, g_Xhi + bo, g_Xlo + bo,
              m0, m0, EDIM, dynsm, acc);
    scores_epilogue(acc, bz, m0, m0, true);
}

// ---------------------------------------------------------------------------
__global__ void __launch_bounds__(256) finalize_kernel(float* __restrict__ out)
{
    const int row = blockIdx.x;
    const float scale = g_diag[row] / g_colsum[row];
    const float4* v = (const float4*)(g_V + (size_t)row * HDIM);
    float4* o = (float4*)(out + (size_t)row * HDIM);
    float4 x = v[threadIdx.x];
    x.x *= scale; x.y *= scale; x.z *= scale; x.w *= scale;
    o[threadIdx.x] = x;
}

__global__ void zero_kernel()
{
    const int i = blockIdx.x * 256 + threadIdx.x;
    if (i < ML) g_colsum[i] = 0.0f;
}

// ---------------------------------------------------------------------------
extern "C" void kernel_launch(void* const* d_in, const int* in_sizes, int n_in,
                              void* d_out, int out_size)
{
    (void)in_sizes; (void)n_in; (void)out_size;
    const float* X  = (const float*)d_in[0];
    const float* Wq = (const float*)d_in[1];
    const float* bq = (const float*)d_in[2];
    const float* Wk = (const float*)d_in[3];
    const float* bk = (const float*)d_in[4];
    const float* Wv = (const float*)d_in[5];
    const float* bv = (const float*)d_in[6];
    float* out = (float*)d_out;

    // Idempotent host-side attribute setup (capture-safe, not stream ops).
    cudaFuncSetAttribute(mgemm_kernel,      cudaFuncAttributeMaxDynamicSharedMemorySize, DYNSMEM);
    cudaFuncSetAttribute(gemm1_kernel,      cudaFuncAttributeMaxDynamicSharedMemorySize, DYNSMEM);
    cudaFuncSetAttribute(gemm2_off_kernel,  cudaFuncAttributeMaxDynamicSharedMemorySize, DYNSMEM);
    cudaFuncSetAttribute(gemm2_diag_kernel, cudaFuncAttributeMaxDynamicSharedMemorySize, DYNSMEM);
    cudaFuncSetAttribute(mgemm_kernel,      cudaFuncAttributePreferredSharedMemoryCarveout, 100);
    cudaFuncSetAttribute(gemm1_kernel,      cudaFuncAttributePreferredSharedMemoryCarveout, 100);
    cudaFuncSetAttribute(gemm2_off_kernel,  cudaFuncAttributePreferredSharedMemoryCarveout, 100);
    cudaFuncSetAttribute(gemm2_diag_kernel, cudaFuncAttributePreferredSharedMemoryCarveout, 100);

    zero_kernel<<<(ML + 255) / 256, 256>>>();

    convx_kernel<<<(ML * EDIM / 4) / 256, 256>>>(X);
    convv_kernel<<<(HDIM * EDIM / 4) / 256, 256>>>(Wv);

    dim3 gt(EDIM / 32, HDIM / 32, 2);
    transw_kernel<<<gt, 256>>>(Wq, Wk);

    dim3 gb(EDIM, 2);
    biasw_kernel<<<gb, 256>>>(bq, bk);
    cscalar_kernel<<<1, 256>>>(bq, bk);

    dim3 gm(EDIM / 128, EDIM / 128);
    mgemm_kernel<<<gm, 256, DYNSMEM>>>();

    alphabeta_kernel<<<ML, 256>>>(X);

    dim3 g1(EDIM / 128, ML / 128, 2);
    gemm1_kernel<<<g1, 256, DYNSMEM>>>(bv);

    dim3 g2(LSEQ / 128, LSEQ / 128, NB);
    gemm2_off_kernel<<<g2, 256, DYNSMEM>>>();

    dim3 g2d(LSEQ / 128, NB);
    gemm2_diag_kernel<<<g2d, 256, DYNSMEM>>>();

    finalize_kernel<<<ML, 256>>>(out);
}

// round 15
// speedup vs baseline: 2.0165x; 1.2428x over previous
#include <cuda_runtime.h>
#include <cuda_bf16.h>
#include <cuda_fp16.h>
#include <math.h>
#include <stdint.h>

#define NB   4
#define LSEQ 4096
#define EDIM 1024
#define HDIM 1024
#define ML   (NB * LSEQ)      // 16384

// ---------------- scratch (static device arrays; no allocation APIs) -------
__device__ __half        g_X16[ML * EDIM];          // 32 MB fp16 X
__device__ __half        g_Qk16[ML * EDIM];         // 32 MB fp16 Qk
__device__ float         g_Qkf[ML * EDIM];          // 64 MB fp32 Qk (diag dot)
__device__ __half        g_Wv16[HDIM * EDIM];       // 2 MB
__device__ __half        g_M16[EDIM * EDIM];        // 2 MB fp16 M^T [e'][e]
__device__ __nv_bfloat16 g_WqThi[EDIM * HDIM];      // Wq^T: [e][h]
__device__ __nv_bfloat16 g_WqTlo[EDIM * HDIM];
__device__ __nv_bfloat16 g_WkThi[EDIM * HDIM];
__device__ __nv_bfloat16 g_WkTlo[EDIM * HDIM];
__device__ float         g_V[ML * HDIM];            // 64 MB
__device__ float         g_w1[EDIM];                // Wq^T * bk
__device__ float         g_w2[EDIM];                // Wk^T * bq
__device__ float         g_alpha[ML];               // X * w1
__device__ float         g_beta[ML];                // X * w2
__device__ float         g_c;                       // bq . bk
__device__ float         g_colsum[ML];
__device__ float         g_diag[ML];

// ---------------- helpers --------------------------------------------------
__device__ __forceinline__ uint32_t smem_u32(const void* p) {
    uint32_t a;
    asm("{ .reg .u64 t; cvta.to.shared.u64 t, %1; cvt.u32.u64 %0, t; }"
        : "=r"(a) : "l"(p));
    return a;
}

__device__ __forceinline__ void cp16(uint32_t s, const void* g) {
    asm volatile("cp.async.cg.shared.global [%0], [%1], 16;" :: "r"(s), "l"(g));
}
#define CP_COMMIT() asm volatile("cp.async.commit_group;" ::: "memory")
#define CP_WAIT2()  asm volatile("cp.async.wait_group 2;" ::: "memory")
#define CP_WAIT1()  asm volatile("cp.async.wait_group 1;" ::: "memory")
#define CP_WAIT0()  asm volatile("cp.async.wait_group 0;" ::: "memory")

__device__ __forceinline__ void ldsm4(uint32_t* a, uint32_t addr) {
    asm volatile("ldmatrix.sync.aligned.m8n8.x4.shared.b16 {%0,%1,%2,%3}, [%4];"
                 : "=r"(a[0]), "=r"(a[1]), "=r"(a[2]), "=r"(a[3]) : "r"(addr));
}
__device__ __forceinline__ void ldsm2(uint32_t* b, uint32_t addr) {
    asm volatile("ldmatrix.sync.aligned.m8n8.x2.shared.b16 {%0,%1}, [%2];"
                 : "=r"(b[0]), "=r"(b[1]) : "r"(addr));
}
__device__ __forceinline__ void mma16816(float* d, const uint32_t* a, const uint32_t* b) {
    asm volatile(
        "mma.sync.aligned.m16n8k16.row.col.f32.bf16.bf16.f32 "
        "{%0,%1,%2,%3}, {%4,%5,%6,%7}, {%8,%9}, {%0,%1,%2,%3};"
        : "+f"(d[0]), "+f"(d[1]), "+f"(d[2]), "+f"(d[3])
        : "r"(a[0]), "r"(a[1]), "r"(a[2]), "r"(a[3]), "r"(b[0]), "r"(b[1]));
}
// fp16 inputs, fp16 accumulate (off-diag scores)
__device__ __forceinline__ void mma16816h(uint32_t* d, const uint32_t* a, const uint32_t* b) {
    asm volatile(
        "mma.sync.aligned.m16n8k16.row.col.f16.f16.f16.f16 "
        "{%0,%1}, {%2,%3,%4,%5}, {%6,%7}, {%0,%1};"
        : "+r"(d[0]), "+r"(d[1])
        : "r"(a[0]), "r"(a[1]), "r"(a[2]), "r"(a[3]), "r"(b[0]), "r"(b[1]));
}
// fp16 inputs, f32 accumulate (Qk and V projections)
__device__ __forceinline__ void mma16816hf(float* d, const uint32_t* a, const uint32_t* b) {
    asm volatile(
        "mma.sync.aligned.m16n8k16.row.col.f32.f16.f16.f32 "
        "{%0,%1,%2,%3}, {%4,%5,%6,%7}, {%8,%9}, {%0,%1,%2,%3};"
        : "+f"(d[0]), "+f"(d[1]), "+f"(d[2]), "+f"(d[3])
        : "r"(a[0]), "r"(a[1]), "r"(a[2]), "r"(a[3]), "r"(b[0]), "r"(b[1]));
}

// ---------------- tiling constants -----------------------------------------
#define PITCH   80                    // bytes per smem row (32 halves + 16B pad)
#define TSZ     (128 * PITCH)         // one operand tile: 10240 B
#define STG3    (4 * TSZ)             // 3-term stage (mgemm): 40960 B
#define STG1    (2 * TSZ)             // 1-term stage: A, B = 20480 B
#define DYNSMEM (2 * STG3)            // 81920 B (== 4 * STG1)

// ---------------------------------------------------------------------------
// run_tile3: 128x128 tile, split-bf16, 2-stage pipe, term-outer mma order.
// (used only by mgemm now)
// ---------------------------------------------------------------------------
__device__ __forceinline__ void run_tile3(
    const __nv_bfloat16* __restrict__ Ah, const __nv_bfloat16* __restrict__ Al,
    const __nv_bfloat16* __restrict__ Bh, const __nv_bfloat16* __restrict__ Bl,
    int m0, int n0, int Kdim, char* sm, float (&acc)[4][4][4])
{
    const int tid  = threadIdx.x;
    const int wid  = tid >> 5, lane = tid & 31;
    const int wm   = wid >> 2, wn = wid & 3;
    const uint32_t sbase = smem_u32(sm);

    const int r  = tid >> 1, cg = tid & 1;
    const size_t ga = (size_t)(m0 + r) * Kdim + cg * 16;
    const size_t gb = (size_t)(n0 + r) * Kdim + cg * 16;
    const uint32_t soff = (uint32_t)(r * PITCH + cg * 32);

    const uint32_t aoff = (uint32_t)((wm * 64 + (lane & 15)) * PITCH + (lane >> 4) * 16);
    const uint32_t boff = (uint32_t)((wn * 32 + (lane & 7)) * PITCH + ((lane >> 3) & 1) * 16);

#define LOADC3(st, kc) do {                                                   \
    const uint32_t s0 = sbase + (uint32_t)(st) * STG3 + soff;                 \
    cp16(s0 + 0 * TSZ,      Ah + ga + (kc));                                  \
    cp16(s0 + 0 * TSZ + 16, Ah + ga + (kc) + 8);                              \
    cp16(s0 + 1 * TSZ,      Al + ga + (kc));                                  \
    cp16(s0 + 1 * TSZ + 16, Al + ga + (kc) + 8);                              \
    cp16(s0 + 2 * TSZ,      Bh + gb + (kc));                                  \
    cp16(s0 + 2 * TSZ + 16, Bh + gb + (kc) + 8);                              \
    cp16(s0 + 3 * TSZ,      Bl + gb + (kc));                                  \
    cp16(s0 + 3 * TSZ + 16, Bl + gb + (kc) + 8);                              \
    CP_COMMIT();                                                              \
} while (0)

    const int NC = Kdim / 32;
    LOADC3(0, 0);

#pragma unroll 1
    for (int c = 0; c < NC; c++) {
        if (c + 1 < NC) { LOADC3((c + 1) & 1, (c + 1) * 32); CP_WAIT1(); }
        else            { CP_WAIT0(); }
        __syncthreads();

        const uint32_t tb = sbase + (uint32_t)(c & 1) * STG3;
#pragma unroll
        for (int k16 = 0; k16 < 2; k16++) {
            uint32_t ah[4][4], al[4][4], bh[4][2], bl[4][2];
#pragma unroll
            for (int mi = 0; mi < 4; mi++) {
                ldsm4(ah[mi], tb + 0 * TSZ + aoff + mi * 16 * PITCH + k16 * 32);
                ldsm4(al[mi], tb + 1 * TSZ + aoff + mi * 16 * PITCH + k16 * 32);
            }
#pragma unroll
            for (int ni = 0; ni < 4; ni++) {
                ldsm2(bh[ni], tb + 2 * TSZ + boff + ni * 8 * PITCH + k16 * 32);
                ldsm2(bl[ni], tb + 3 * TSZ + boff + ni * 8 * PITCH + k16 * 32);
            }
#pragma unroll
            for (int mi = 0; mi < 4; mi++)
#pragma unroll
                for (int ni = 0; ni < 4; ni++)
                    mma16816(acc[mi][ni], ah[mi], bh[ni]);
#pragma unroll
            for (int mi = 0; mi < 4; mi++)
#pragma unroll
                for (int ni = 0; ni < 4; ni++)
                    mma16816(acc[mi][ni], ah[mi], bl[ni]);
#pragma unroll
            for (int mi = 0; mi < 4; mi++)
#pragma unroll
                for (int ni = 0; ni < 4; ni++)
                    mma16816(acc[mi][ni], al[mi], bh[ni]);
        }
        __syncthreads();
    }
#undef LOADC3
}

// ---------------------------------------------------------------------------
// run_tile_h: 128x128 tile, fp16 in / fp16 acc, 4-stage pipe, 1 sync/chunk.
// ---------------------------------------------------------------------------
__device__ __forceinline__ void run_tile_h(
    const __half* __restrict__ A, const __half* __restrict__ B,
    int m0, int n0, int Kdim, char* sm, uint32_t (&acc)[4][4][2])
{
    const int tid  = threadIdx.x;
    const int wid  = tid >> 5, lane = tid & 31;
    const int wm   = wid >> 2, wn = wid & 3;
    const uint32_t sbase = smem_u32(sm);

    const int r  = tid >> 1, cg = tid & 1;
    const size_t ga = (size_t)(m0 + r) * Kdim + cg * 16;
    const size_t gb = (size_t)(n0 + r) * Kdim + cg * 16;
    const uint32_t soff = (uint32_t)(r * PITCH + cg * 32);

    const uint32_t aoff = (uint32_t)((wm * 64 + (lane & 15)) * PITCH + (lane >> 4) * 16);
    const uint32_t boff = (uint32_t)((wn * 32 + (lane & 7)) * PITCH + ((lane >> 3) & 1) * 16);

#define LOADCH(st, kc) do {                                                   \
    const uint32_t s0 = sbase + (uint32_t)(st) * STG1 + soff;                 \
    cp16(s0,            A + ga + (kc));                                       \
    cp16(s0 + 16,       A + ga + (kc) + 8);                                   \
    cp16(s0 + TSZ,      B + gb + (kc));                                       \
    cp16(s0 + TSZ + 16, B + gb + (kc) + 8);                                   \
    CP_COMMIT();                                                              \
} while (0)

    const int NC = Kdim / 32;
    LOADCH(0, 0);
    LOADCH(1, 32);
    LOADCH(2, 64);

#pragma unroll 1
    for (int c = 0; c < NC; c++) {
        CP_WAIT2();
        __syncthreads();
        const uint32_t tb = sbase + (uint32_t)(c & 3) * STG1;
#pragma unroll
        for (int k16 = 0; k16 < 2; k16++) {
            uint32_t ah[4][4], bh[4][2];
#pragma unroll
            for (int mi = 0; mi < 4; mi++)
                ldsm4(ah[mi], tb + aoff + mi * 16 * PITCH + k16 * 32);
#pragma unroll
            for (int ni = 0; ni < 4; ni++)
                ldsm2(bh[ni], tb + TSZ + boff + ni * 8 * PITCH + k16 * 32);
#pragma unroll
            for (int mi = 0; mi < 4; mi++)
#pragma unroll
                for (int ni = 0; ni < 4; ni++)
                    mma16816h(acc[mi][ni], ah[mi], bh[ni]);
        }
        if (c + 3 < NC) LOADCH((c + 3) & 3, (c + 3) * 32);
    }
#undef LOADCH
}

// ---------------------------------------------------------------------------
// run_tile_h32: fp16 in / f32 acc, 4-stage pipe (Qk and V projections).
// ---------------------------------------------------------------------------
__device__ __forceinline__ void run_tile_h32(
    const __half* __restrict__ A, const __half* __restrict__ B,
    int m0, int n0, int Kdim, char* sm, float (&acc)[4][4][4])
{
    const int tid  = threadIdx.x;
    const int wid  = tid >> 5, lane = tid & 31;
    const int wm   = wid >> 2, wn = wid & 3;
    const uint32_t sbase = smem_u32(sm);

    const int r  = tid >> 1, cg = tid & 1;
    const size_t ga = (size_t)(m0 + r) * Kdim + cg * 16;
    const size_t gb = (size_t)(n0 + r) * Kdim + cg * 16;
    const uint32_t soff = (uint32_t)(r * PITCH + cg * 32);

    const uint32_t aoff = (uint32_t)((wm * 64 + (lane & 15)) * PITCH + (lane >> 4) * 16);
    const uint32_t boff = (uint32_t)((wn * 32 + (lane & 7)) * PITCH + ((lane >> 3) & 1) * 16);

#define LOADCF(st, kc) do {                                                   \
    const uint32_t s0 = sbase + (uint32_t)(st) * STG1 + soff;                 \
    cp16(s0,            A + ga + (kc));                                       \
    cp16(s0 + 16,       A + ga + (kc) + 8);                                   \
    cp16(s0 + TSZ,      B + gb + (kc));                                       \
    cp16(s0 + TSZ + 16, B + gb + (kc) + 8);                                   \
    CP_COMMIT();                                                              \
} while (0)

    const int NC = Kdim / 32;
    LOADCF(0, 0);
    LOADCF(1, 32);
    LOADCF(2, 64);

#pragma unroll 1
    for (int c = 0; c < NC; c++) {
        CP_WAIT2();
        __syncthreads();
        const uint32_t tb = sbase + (uint32_t)(c & 3) * STG1;
#pragma unroll
        for (int k16 = 0; k16 < 2; k16++) {
            uint32_t ah[4][4], bh[4][2];
#pragma unroll
            for (int mi = 0; mi < 4; mi++)
                ldsm4(ah[mi], tb + aoff + mi * 16 * PITCH + k16 * 32);
#pragma unroll
            for (int ni = 0; ni < 4; ni++)
                ldsm2(bh[ni], tb + TSZ + boff + ni * 8 * PITCH + k16 * 32);
#pragma unroll
            for (int mi = 0; mi < 4; mi++)
#pragma unroll
                for (int ni = 0; ni < 4; ni++)
                    mma16816hf(acc[mi][ni], ah[mi], bh[ni]);
        }
        if (c + 3 < NC) LOADCF((c + 3) & 3, (c + 3) * 32);
    }
#undef LOADCF
}

// ---------------------------------------------------------------------------
// Conversions / transposes
// ---------------------------------------------------------------------------
__global__ void __launch_bounds__(256) convx_kernel(const float* __restrict__ X) {
    const size_t i = (size_t)blockIdx.x * 256 + threadIdx.x;
    float4 v = ((const float4*)X)[i];
    ((__half2*)g_X16)[2 * i]     = __floats2half2_rn(v.x, v.y);
    ((__half2*)g_X16)[2 * i + 1] = __floats2half2_rn(v.z, v.w);
}

__global__ void __launch_bounds__(256) convv_kernel(const float* __restrict__ Wv) {
    const size_t i = (size_t)blockIdx.x * 256 + threadIdx.x;
    float4 v = ((const float4*)Wv)[i];
    ((__half2*)g_Wv16)[2 * i]     = __floats2half2_rn(v.x, v.y);
    ((__half2*)g_Wv16)[2 * i + 1] = __floats2half2_rn(v.z, v.w);
}

// Transposed split copies of Wq, Wk: WT[e][h] = W[h][e], bf16 hi/lo.
__global__ void __launch_bounds__(256) transw_kernel(
    const float* __restrict__ Wq, const float* __restrict__ Wk)
{
    __shared__ float t[32][33];
    const int z = blockIdx.z;
    const float* W = z ? Wk : Wq;
    __nv_bfloat16* Th = z ? g_WkThi : g_WqThi;
    __nv_bfloat16* Tl = z ? g_WkTlo : g_WqTlo;
    const int e0 = blockIdx.x * 32, h0 = blockIdx.y * 32;
    const int tx = threadIdx.x & 31, ty = threadIdx.x >> 5;  // 32 x 8

#pragma unroll
    for (int i = ty; i < 32; i += 8)
        t[i][tx] = W[(size_t)(h0 + i) * EDIM + e0 + tx];
    __syncthreads();
#pragma unroll
    for (int i = ty; i < 32; i += 8) {
        float v = t[tx][i];                 // = W[h0+tx][e0+i]
        __nv_bfloat16 h = __float2bfloat16(v);
        __nv_bfloat16 l = __float2bfloat16(v - __bfloat162float(h));
        Th[(size_t)(e0 + i) * HDIM + h0 + tx] = h;
        Tl[(size_t)(e0 + i) * HDIM + h0 + tx] = l;
    }
}

// w1[e] = sum_h Wq[h,e]*bk[h],  w2[e] = sum_h Wk[h,e]*bq[h]
__global__ void __launch_bounds__(256) biasw_kernel(
    const float* __restrict__ bq, const float* __restrict__ bk)
{
    __shared__ float red[8];
    const int e = blockIdx.x, z = blockIdx.y;
    const __nv_bfloat16* Th = z ? g_WkThi : g_WqThi;
    const __nv_bfloat16* Tl = z ? g_WkTlo : g_WqTlo;
    const float* b = z ? bq : bk;
    float s = 0.0f;
    for (int h = threadIdx.x; h < HDIM; h += 256)
        s += (__bfloat162float(Th[(size_t)e * HDIM + h]) +
              __bfloat162float(Tl[(size_t)e * HDIM + h])) * b[h];
#pragma unroll
    for (int m = 16; m >= 1; m >>= 1) s += __shfl_xor_sync(0xffffffffu, s, m);
    if ((threadIdx.x & 31) == 0) red[threadIdx.x >> 5] = s;
    __syncthreads();
    if (threadIdx.x == 0) {
        float t = 0.0f;
#pragma unroll
        for (int i = 0; i < 8; i++) t += red[i];
        (z ? g_w2 : g_w1)[e] = t;
    }
}

__global__ void cscalar_kernel(const float* __restrict__ bq,
                               const float* __restrict__ bk)
{
    __shared__ float red[8];
    float s = 0.0f;
    for (int h = threadIdx.x; h < HDIM; h += 256) s += bq[h] * bk[h];
#pragma unroll
    for (int m = 16; m >= 1; m >>= 1) s += __shfl_xor_sync(0xffffffffu, s, m);
    if ((threadIdx.x & 31) == 0) red[threadIdx.x >> 5] = s;
    __syncthreads();
    if (threadIdx.x == 0) {
        float t = 0.0f;
#pragma unroll
        for (int i = 0; i < 8; i++) t += red[i];
        g_c = t;
    }
}

// alpha[l] = X[l].w1, beta[l] = X[l].w2  (exact fp32 inputs)
__global__ void __launch_bounds__(256) alphabeta_kernel(const float* __restrict__ X)
{
    __shared__ float reda[8], redb[8];
    const int l = blockIdx.x;
    float sa = 0.0f, sb = 0.0f;
    for (int e = threadIdx.x; e < EDIM; e += 256) {
        float x = X[(size_t)l * EDIM + e];
        sa += x * g_w1[e];
        sb += x * g_w2[e];
    }
#pragma unroll
    for (int m = 16; m >= 1; m >>= 1) {
        sa += __shfl_xor_sync(0xffffffffu, sa, m);
        sb += __shfl_xor_sync(0xffffffffu, sb, m);
    }
    if ((threadIdx.x & 31) == 0) { reda[threadIdx.x >> 5] = sa; redb[threadIdx.x >> 5] = sb; }
    __syncthreads();
    if (threadIdx.x == 0) {
        float ta = 0.0f, tb = 0.0f;
#pragma unroll
        for (int i = 0; i < 8; i++) { ta += reda[i]; tb += redb[i]; }
        g_alpha[l] = ta;
        g_beta[l]  = tb;
    }
}

// ---------------------------------------------------------------------------
// mgemm: Mt[e'][e] = sum_h Wk[h,e']*Wq[h,e]  (3-term bf16 -> fp16 out).
// grid (8, 8)
// ---------------------------------------------------------------------------
__global__ void __launch_bounds__(256, 2) mgemm_kernel()
{
    extern __shared__ char dynsm[];
    const int m0 = blockIdx.y * 128;   // e'
    const int n0 = blockIdx.x * 128;   // e

    float acc[4][4][4];
#pragma unroll
    for (int a = 0; a < 4; a++)
#pragma unroll
        for (int b = 0; b < 4; b++)
#pragma unroll
            for (int cc = 0; cc < 4; cc++) acc[a][b][cc] = 0.0f;

    run_tile3(g_WkThi, g_WkTlo, g_WqThi, g_WqTlo, m0, n0, HDIM, dynsm, acc);

    const int tid = threadIdx.x;
    const int wid = tid >> 5, lane = tid & 31;
    const int wm = wid >> 2, wn = wid & 3;

#pragma unroll
    for (int mi = 0; mi < 4; mi++) {
        const int r0 = m0 + wm * 64 + mi * 16 + (lane >> 2);
#pragma unroll
        for (int ni = 0; ni < 4; ni++) {
            const int gc = n0 + wn * 32 + ni * 8 + 2 * (lane & 3);
#pragma unroll
            for (int hh = 0; hh < 2; hh++) {
                const int rr = r0 + hh * 8;
                *(__half2*)(g_M16 + (size_t)rr * EDIM + gc) =
                    __floats2half2_rn(acc[mi][ni][2 * hh], acc[mi][ni][2 * hh + 1]);
            }
        }
    }
}

// ---------------------------------------------------------------------------
// GEMM1: z=0: Qk = X16*M16^T (fp16 in, f32 acc; writes Qkf fp32 + Qk16 fp16)
//        z=1: V = X16*Wv16^T + bv (fp32 out)
// grid (8, 128, 2)
// ---------------------------------------------------------------------------
__global__ void __launch_bounds__(256, 2) gemm1_kernel(const float* __restrict__ bv)
{
    extern __shared__ char dynsm[];
    const int z  = blockIdx.z;
    const int m0 = blockIdx.y * 128;
    const int n0 = blockIdx.x * 128;

    float acc[4][4][4];
#pragma unroll
    for (int a = 0; a < 4; a++)
#pragma unroll
        for (int b = 0; b < 4; b++)
#pragma unroll
            for (int cc = 0; cc < 4; cc++) acc[a][b][cc] = 0.0f;

    run_tile_h32(g_X16, z ? g_Wv16 : g_M16, m0, n0, EDIM, dynsm, acc);

    const int tid = threadIdx.x;
    const int wid = tid >> 5, lane = tid & 31;
    const int wm = wid >> 2, wn = wid & 3;

#pragma unroll
    for (int mi = 0; mi < 4; mi++) {
        const int r0 = m0 + wm * 64 + mi * 16 + (lane >> 2);
#pragma unroll
        for (int ni = 0; ni < 4; ni++) {
            const int gc = n0 + wn * 32 + ni * 8 + 2 * (lane & 3);
            if (z == 1) {
                const float b0 = __ldg(&bv[gc]), b1 = __ldg(&bv[gc + 1]);
                *(float2*)(g_V + (size_t)r0 * HDIM + gc) =
                    make_float2(acc[mi][ni][0] + b0, acc[mi][ni][1] + b1);
                *(float2*)(g_V + (size_t)(r0 + 8) * HDIM + gc) =
                    make_float2(acc[mi][ni][2] + b0, acc[mi][ni][3] + b1);
            } else {
#pragma unroll
                for (int hh = 0; hh < 2; hh++) {
                    const int rr = r0 + hh * 8;
                    const float v0 = acc[mi][ni][2 * hh], v1 = acc[mi][ni][2 * hh + 1];
                    *(float2*)(g_Qkf + (size_t)rr * EDIM + gc) = make_float2(v0, v1);
                    *(__half2*)(g_Qk16 + (size_t)rr * EDIM + gc) = __floats2half2_rn(v0, v1);
                }
            }
        }
    }
}

// ---------------------------------------------------------------------------
// Diagonal: D[l] = Qkf[l] . X[l] (fp32); g_diag[l] = exp((D+a+b+c)*sc)
// grid ML, block 256
// ---------------------------------------------------------------------------
__global__ void __launch_bounds__(256) diagdot_kernel(const float* __restrict__ X)
{
    __shared__ float red[8];
    const int l = blockIdx.x;
    const float4* q = (const float4*)(g_Qkf + (size_t)l * EDIM);
    const float4* x = (const float4*)(X + (size_t)l * EDIM);
    float s = 0.0f;
    for (int i = threadIdx.x; i < EDIM / 4; i += 256) {
        float4 a = q[i], b = x[i];
        s += a.x * b.x + a.y * b.y + a.z * b.z + a.w * b.w;
    }
#pragma unroll
    for (int m = 16; m >= 1; m >>= 1) s += __shfl_xor_sync(0xffffffffu, s, m);
    if ((threadIdx.x & 31) == 0) red[threadIdx.x >> 5] = s;
    __syncthreads();
    if (threadIdx.x == 0) {
        float t = 0.0f;
#pragma unroll
        for (int i = 0; i < 8; i++) t += red[i];
        const float sc = 0.015625f;
        g_diag[l] = __expf((t + g_alpha[l] + g_beta[l] + g_c) * sc);
    }
}

// ---------------------------------------------------------------------------
// GEMM2: all tiles. S = Qk16 * X16^T (fp16 in, fp16 acc); exp + colsum.
// grid (32, 32, NB)
// ---------------------------------------------------------------------------
__global__ void __launch_bounds__(256, 2) gemm2_kernel()
{
    extern __shared__ char dynsm[];
    __shared__ float sred[128];

    const int bz = blockIdx.z;
    const int m0 = blockIdx.y * 128;
    const int n0 = blockIdx.x * 128;
    const int tid = threadIdx.x;
    const size_t bo = (size_t)bz * LSEQ * EDIM;

    if (tid < 128) sred[tid] = 0.0f;

    uint32_t acch[4][4][2];
#pragma unroll
    for (int a = 0; a < 4; a++)
#pragma unroll
        for (int b = 0; b < 4; b++) { acch[a][b][0] = 0; acch[a][b][1] = 0; }

    run_tile_h(g_Qk16 + bo, g_X16 + bo, m0, n0, EDIM, dynsm, acch);

    const int wid = tid >> 5, lane = tid & 31;
    const int wm = wid >> 2, wn = wid & 3;
    const float sc = 0.015625f;
    const float cc = g_c;

    float2 csum[4];
#pragma unroll
    for (int ni = 0; ni < 4; ni++) csum[ni] = make_float2(0.0f, 0.0f);

#pragma unroll
    for (int mi = 0; mi < 4; mi++) {
        const int lr = wm * 64 + mi * 16 + (lane >> 2);
        const float a0 = g_alpha[(size_t)bz * LSEQ + m0 + lr];
        const float a1 = g_alpha[(size_t)bz * LSEQ + m0 + lr + 8];
#pragma unroll
        for (int ni = 0; ni < 4; ni++) {
            const int lc = wn * 32 + ni * 8 + 2 * (lane & 3);
            const float b0 = g_beta[(size_t)bz * LSEQ + n0 + lc];
            const float b1 = g_beta[(size_t)bz * LSEQ + n0 + lc + 1];
            const __half2 p0 = *reinterpret_cast<__half2*>(&acch[mi][ni][0]);
            const __half2 p1 = *reinterpret_cast<__half2*>(&acch[mi][ni][1]);
            csum[ni].x += __expf((__half2float(p0.x) + a0 + b0 + cc) * sc)
                        + __expf((__half2float(p1.x) + a1 + b0 + cc) * sc);
            csum[ni].y += __expf((__half2float(p0.y) + a0 + b1 + cc) * sc)
                        + __expf((__half2float(p1.y) + a1 + b1 + cc) * sc);
        }
    }

    __syncthreads();   // sred init visible

#pragma unroll
    for (int ni = 0; ni < 4; ni++) {
#pragma unroll
        for (int m = 4; m <= 16; m <<= 1) {
            csum[ni].x += __shfl_xor_sync(0xffffffffu, csum[ni].x, m);
            csum[ni].y += __shfl_xor_sync(0xffffffffu, csum[ni].y, m);
        }
        if (lane < 4) {
            atomicAdd(&sred[wn * 32 + ni * 8 + 2 * lane],     csum[ni].x);
            atomicAdd(&sred[wn * 32 + ni * 8 + 2 * lane + 1], csum[ni].y);
        }
    }

    __syncthreads();
    if (tid < 128)
        atomicAdd(&g_colsum[(size_t)bz * LSEQ + n0 + tid], sred[tid]);
}

// ---------------------------------------------------------------------------
__global__ void __launch_bounds__(256) finalize_kernel(float* __restrict__ out)
{
    const int row = blockIdx.x;
    const float scale = g_diag[row] / g_colsum[row];
    const float4* v = (const float4*)(g_V + (size_t)row * HDIM);
    float4* o = (float4*)(out + (size_t)row * HDIM);
    float4 x = v[threadIdx.x];
    x.x *= scale; x.y *= scale; x.z *= scale; x.w *= scale;
    o[threadIdx.x] = x;
}

__global__ void zero_kernel()
{
    const int i = blockIdx.x * 256 + threadIdx.x;
    if (i < ML) g_colsum[i] = 0.0f;
}

// ---------------------------------------------------------------------------
extern "C" void kernel_launch(void* const* d_in, const int* in_sizes, int n_in,
                              void* d_out, int out_size)
{
    (void)in_sizes; (void)n_in; (void)out_size;
    const float* X  = (const float*)d_in[0];
    const float* Wq = (const float*)d_in[1];
    const float* bq = (const float*)d_in[2];
    const float* Wk = (const float*)d_in[3];
    const float* bk = (const float*)d_in[4];
    const float* Wv = (const float*)d_in[5];
    const float* bv = (const float*)d_in[6];
    float* out = (float*)d_out;

    // Idempotent host-side attribute setup (capture-safe, not stream ops).
    cudaFuncSetAttribute(mgemm_kernel,  cudaFuncAttributeMaxDynamicSharedMemorySize, DYNSMEM);
    cudaFuncSetAttribute(gemm1_kernel,  cudaFuncAttributeMaxDynamicSharedMemorySize, DYNSMEM);
    cudaFuncSetAttribute(gemm2_kernel,  cudaFuncAttributeMaxDynamicSharedMemorySize, DYNSMEM);
    cudaFuncSetAttribute(mgemm_kernel,  cudaFuncAttributePreferredSharedMemoryCarveout, 100);
    cudaFuncSetAttribute(gemm1_kernel,  cudaFuncAttributePreferredSharedMemoryCarveout, 100);
    cudaFuncSetAttribute(gemm2_kernel,  cudaFuncAttributePreferredSharedMemoryCarveout, 100);

    zero_kernel<<<(ML + 255) / 256, 256>>>();

    convx_kernel<<<(ML * EDIM / 4) / 256, 256>>>(X);
    convv_kernel<<<(HDIM * EDIM / 4) / 256, 256>>>(Wv);

    dim3 gt(EDIM / 32, HDIM / 32, 2);
    transw_kernel<<<gt, 256>>>(Wq, Wk);

    dim3 gb(EDIM, 2);
    biasw_kernel<<<gb, 256>>>(bq, bk);
    cscalar_kernel<<<1, 256>>>(bq, bk);

    dim3 gm(EDIM / 128, EDIM / 128);
    mgemm_kernel<<<gm, 256, DYNSMEM>>>();

    alphabeta_kernel<<<ML, 256>>>(X);

    dim3 g1(EDIM / 128, ML / 128, 2);
    gemm1_kernel<<<g1, 256, DYNSMEM>>>(bv);

    diagdot_kernel<<<ML, 256>>>(X);

    dim3 g2(LSEQ / 128, LSEQ / 128, NB);
    gemm2_kernel<<<g2, 256, DYNSMEM>>>();

    finalize_kernel<<<ML, 256>>>(out);
}

// round 16
// speedup vs baseline: 2.0943x; 1.0386x over previous
#include <cuda_runtime.h>
#include <cuda_fp16.h>
#include <math.h>
#include <stdint.h>

#define NB   4
#define LSEQ 4096
#define EDIM 1024
#define HDIM 1024
#define ML   (NB * LSEQ)      // 16384

// ---------------- scratch (static device arrays; no allocation APIs) -------
__device__ __half        g_X16[ML * EDIM];          // 32 MB fp16 X
__device__ __half        g_Qk16[ML * EDIM];         // 32 MB fp16 Qk
__device__ float         g_Qkf[ML * EDIM];          // 64 MB fp32 Qk (diag dot)
__device__ __half        g_Wv16[HDIM * EDIM];       // 2 MB
__device__ __half        g_M16[EDIM * EDIM];        // 2 MB fp16 M^T [e'][e]
__device__ __half        g_WqT16[EDIM * HDIM];      // Wq^T fp16 [e][h]
__device__ __half        g_WkT16[EDIM * HDIM];      // Wk^T fp16 [e][h]
__device__ float         g_V[ML * HDIM];            // 64 MB
__device__ float         g_w1[EDIM];                // Wq^T * bk
__device__ float         g_w2[EDIM];                // Wk^T * bq
__device__ float         g_alpha[ML];               // X * w1
__device__ float         g_beta[ML];                // X * w2
__device__ float         g_c;                       // bq . bk
__device__ float         g_colsum[ML];
__device__ float         g_diag[ML];

// ---------------- helpers --------------------------------------------------
__device__ __forceinline__ uint32_t smem_u32(const void* p) {
    uint32_t a;
    asm("{ .reg .u64 t; cvta.to.shared.u64 t, %1; cvt.u32.u64 %0, t; }"
        : "=r"(a) : "l"(p));
    return a;
}

__device__ __forceinline__ void cp16(uint32_t s, const void* g) {
    asm volatile("cp.async.cg.shared.global [%0], [%1], 16;" :: "r"(s), "l"(g));
}
#define CP_COMMIT() asm volatile("cp.async.commit_group;" ::: "memory")
#define CP_WAIT2()  asm volatile("cp.async.wait_group 2;" ::: "memory")
#define CP_WAIT0()  asm volatile("cp.async.wait_group 0;" ::: "memory")

__device__ __forceinline__ void ldsm4(uint32_t* a, uint32_t addr) {
    asm volatile("ldmatrix.sync.aligned.m8n8.x4.shared.b16 {%0,%1,%2,%3}, [%4];"
                 : "=r"(a[0]), "=r"(a[1]), "=r"(a[2]), "=r"(a[3]) : "r"(addr));
}
__device__ __forceinline__ void ldsm2(uint32_t* b, uint32_t addr) {
    asm volatile("ldmatrix.sync.aligned.m8n8.x2.shared.b16 {%0,%1}, [%2];"
                 : "=r"(b[0]), "=r"(b[1]) : "r"(addr));
}
// fp16 inputs, fp16 accumulate (scores)
__device__ __forceinline__ void mma16816h(uint32_t* d, const uint32_t* a, const uint32_t* b) {
    asm volatile(
        "mma.sync.aligned.m16n8k16.row.col.f16.f16.f16.f16 "
        "{%0,%1}, {%2,%3,%4,%5}, {%6,%7}, {%0,%1};"
        : "+r"(d[0]), "+r"(d[1])
        : "r"(a[0]), "r"(a[1]), "r"(a[2]), "r"(a[3]), "r"(b[0]), "r"(b[1]));
}
// fp16 inputs, f32 accumulate (Qk, V, M projections)
__device__ __forceinline__ void mma16816hf(float* d, const uint32_t* a, const uint32_t* b) {
    asm volatile(
        "mma.sync.aligned.m16n8k16.row.col.f32.f16.f16.f32 "
        "{%0,%1,%2,%3}, {%4,%5,%6,%7}, {%8,%9}, {%0,%1,%2,%3};"
        : "+f"(d[0]), "+f"(d[1]), "+f"(d[2]), "+f"(d[3])
        : "r"(a[0]), "r"(a[1]), "r"(a[2]), "r"(a[3]), "r"(b[0]), "r"(b[1]));
}

// ---------------- tiling constants -----------------------------------------
#define PITCH   80                    // bytes per smem row (32 halves + 16B pad)
#define TSZ     (128 * PITCH)         // one operand tile: 10240 B
#define STG1    (2 * TSZ)             // stage: A, B = 20480 B
#define DYNSMEM (4 * STG1)            // 81920 B (4-stage)

// ---------------------------------------------------------------------------
// run_tile_h: 128x128 tile, fp16 in / fp16 acc, 4-stage pipe, 1 sync/chunk.
// ---------------------------------------------------------------------------
__device__ __forceinline__ void run_tile_h(
    const __half* __restrict__ A, const __half* __restrict__ B,
    int m0, int n0, int Kdim, char* sm, uint32_t (&acc)[4][4][2])
{
    const int tid  = threadIdx.x;
    const int wid  = tid >> 5, lane = tid & 31;
    const int wm   = wid >> 2, wn = wid & 3;
    const uint32_t sbase = smem_u32(sm);

    const int r  = tid >> 1, cg = tid & 1;
    const size_t ga = (size_t)(m0 + r) * Kdim + cg * 16;
    const size_t gb = (size_t)(n0 + r) * Kdim + cg * 16;
    const uint32_t soff = (uint32_t)(r * PITCH + cg * 32);

    const uint32_t aoff = (uint32_t)((wm * 64 + (lane & 15)) * PITCH + (lane >> 4) * 16);
    const uint32_t boff = (uint32_t)((wn * 32 + (lane & 7)) * PITCH + ((lane >> 3) & 1) * 16);

#define LOADCH(st, kc) do {                                                   \
    const uint32_t s0 = sbase + (uint32_t)(st) * STG1 + soff;                 \
    cp16(s0,            A + ga + (kc));                                       \
    cp16(s0 + 16,       A + ga + (kc) + 8);                                   \
    cp16(s0 + TSZ,      B + gb + (kc));                                       \
    cp16(s0 + TSZ + 16, B + gb + (kc) + 8);                                   \
    CP_COMMIT();                                                              \
} while (0)

    const int NC = Kdim / 32;
    LOADCH(0, 0);
    LOADCH(1, 32);
    LOADCH(2, 64);

#pragma unroll 1
    for (int c = 0; c < NC; c++) {
        CP_WAIT2();
        __syncthreads();
        const uint32_t tb = sbase + (uint32_t)(c & 3) * STG1;
#pragma unroll
        for (int k16 = 0; k16 < 2; k16++) {
            uint32_t ah[4][4], bh[4][2];
#pragma unroll
            for (int mi = 0; mi < 4; mi++)
                ldsm4(ah[mi], tb + aoff + mi * 16 * PITCH + k16 * 32);
#pragma unroll
            for (int ni = 0; ni < 4; ni++)
                ldsm2(bh[ni], tb + TSZ + boff + ni * 8 * PITCH + k16 * 32);
#pragma unroll
            for (int mi = 0; mi < 4; mi++)
#pragma unroll
                for (int ni = 0; ni < 4; ni++)
                    mma16816h(acc[mi][ni], ah[mi], bh[ni]);
        }
        if (c + 3 < NC) LOADCH((c + 3) & 3, (c + 3) * 32);
    }
#undef LOADCH
}

// ---------------------------------------------------------------------------
// run_tile_h32: fp16 in / f32 acc, 4-stage pipe (Qk, V, M projections).
// ---------------------------------------------------------------------------
__device__ __forceinline__ void run_tile_h32(
    const __half* __restrict__ A, const __half* __restrict__ B,
    int m0, int n0, int Kdim, char* sm, float (&acc)[4][4][4])
{
    const int tid  = threadIdx.x;
    const int wid  = tid >> 5, lane = tid & 31;
    const int wm   = wid >> 2, wn = wid & 3;
    const uint32_t sbase = smem_u32(sm);

    const int r  = tid >> 1, cg = tid & 1;
    const size_t ga = (size_t)(m0 + r) * Kdim + cg * 16;
    const size_t gb = (size_t)(n0 + r) * Kdim + cg * 16;
    const uint32_t soff = (uint32_t)(r * PITCH + cg * 32);

    const uint32_t aoff = (uint32_t)((wm * 64 + (lane & 15)) * PITCH + (lane >> 4) * 16);
    const uint32_t boff = (uint32_t)((wn * 32 + (lane & 7)) * PITCH + ((lane >> 3) & 1) * 16);

#define LOADCF(st, kc) do {                                                   \
    const uint32_t s0 = sbase + (uint32_t)(st) * STG1 + soff;                 \
    cp16(s0,            A + ga + (kc));                                       \
    cp16(s0 + 16,       A + ga + (kc) + 8);                                   \
    cp16(s0 + TSZ,      B + gb + (kc));                                       \
    cp16(s0 + TSZ + 16, B + gb + (kc) + 8);                                   \
    CP_COMMIT();                                                              \
} while (0)

    const int NC = Kdim / 32;
    LOADCF(0, 0);
    LOADCF(1, 32);
    LOADCF(2, 64);

#pragma unroll 1
    for (int c = 0; c < NC; c++) {
        CP_WAIT2();
        __syncthreads();
        const uint32_t tb = sbase + (uint32_t)(c & 3) * STG1;
#pragma unroll
        for (int k16 = 0; k16 < 2; k16++) {
            uint32_t ah[4][4], bh[4][2];
#pragma unroll
            for (int mi = 0; mi < 4; mi++)
                ldsm4(ah[mi], tb + aoff + mi * 16 * PITCH + k16 * 32);
#pragma unroll
            for (int ni = 0; ni < 4; ni++)
                ldsm2(bh[ni], tb + TSZ + boff + ni * 8 * PITCH + k16 * 32);
#pragma unroll
            for (int mi = 0; mi < 4; mi++)
#pragma unroll
                for (int ni = 0; ni < 4; ni++)
                    mma16816hf(acc[mi][ni], ah[mi], bh[ni]);
        }
        if (c + 3 < NC) LOADCF((c + 3) & 3, (c + 3) * 32);
    }
#undef LOADCF
}

// ---------------------------------------------------------------------------
// Conversions / transposes
// ---------------------------------------------------------------------------
__global__ void __launch_bounds__(256) convx_kernel(const float* __restrict__ X) {
    const size_t i = (size_t)blockIdx.x * 256 + threadIdx.x;
    float4 v = ((const float4*)X)[i];
    ((__half2*)g_X16)[2 * i]     = __floats2half2_rn(v.x, v.y);
    ((__half2*)g_X16)[2 * i + 1] = __floats2half2_rn(v.z, v.w);
}

__global__ void __launch_bounds__(256) convv_kernel(const float* __restrict__ Wv) {
    const size_t i = (size_t)blockIdx.x * 256 + threadIdx.x;
    float4 v = ((const float4*)Wv)[i];
    ((__half2*)g_Wv16)[2 * i]     = __floats2half2_rn(v.x, v.y);
    ((__half2*)g_Wv16)[2 * i + 1] = __floats2half2_rn(v.z, v.w);
}

// Transposed fp16 copies of Wq, Wk: WT[e][h] = W[h][e].
__global__ void __launch_bounds__(256) transw_kernel(
    const float* __restrict__ Wq, const float* __restrict__ Wk)
{
    __shared__ float t[32][33];
    const int z = blockIdx.z;
    const float* W = z ? Wk : Wq;
    __half* T = z ? g_WkT16 : g_WqT16;
    const int e0 = blockIdx.x * 32, h0 = blockIdx.y * 32;
    const int tx = threadIdx.x & 31, ty = threadIdx.x >> 5;  // 32 x 8

#pragma unroll
    for (int i = ty; i < 32; i += 8)
        t[i][tx] = W[(size_t)(h0 + i) * EDIM + e0 + tx];
    __syncthreads();
#pragma unroll
    for (int i = ty; i < 32; i += 8)
        T[(size_t)(e0 + i) * HDIM + h0 + tx] = __float2half_rn(t[tx][i]);
}

// w1[e] = sum_h Wq[h,e]*bk[h],  w2[e] = sum_h Wk[h,e]*bq[h]
__global__ void __launch_bounds__(256) biasw_kernel(
    const float* __restrict__ bq, const float* __restrict__ bk)
{
    __shared__ float red[8];
    const int e = blockIdx.x, z = blockIdx.y;
    const __half* T = z ? g_WkT16 : g_WqT16;
    const float* b = z ? bq : bk;
    float s = 0.0f;
    for (int h = threadIdx.x; h < HDIM; h += 256)
        s += __half2float(T[(size_t)e * HDIM + h]) * b[h];
#pragma unroll
    for (int m = 16; m >= 1; m >>= 1) s += __shfl_xor_sync(0xffffffffu, s, m);
    if ((threadIdx.x & 31) == 0) red[threadIdx.x >> 5] = s;
    __syncthreads();
    if (threadIdx.x == 0) {
        float t = 0.0f;
#pragma unroll
        for (int i = 0; i < 8; i++) t += red[i];
        (z ? g_w2 : g_w1)[e] = t;
    }
}

__global__ void cscalar_kernel(const float* __restrict__ bq,
                               const float* __restrict__ bk)
{
    __shared__ float red[8];
    float s = 0.0f;
    for (int h = threadIdx.x; h < HDIM; h += 256) s += bq[h] * bk[h];
#pragma unroll
    for (int m = 16; m >= 1; m >>= 1) s += __shfl_xor_sync(0xffffffffu, s, m);
    if ((threadIdx.x & 31) == 0) red[threadIdx.x >> 5] = s;
    __syncthreads();
    if (threadIdx.x == 0) {
        float t = 0.0f;
#pragma unroll
        for (int i = 0; i < 8; i++) t += red[i];
        g_c = t;
    }
}

// alpha[l] = X[l].w1, beta[l] = X[l].w2  (exact fp32 inputs)
__global__ void __launch_bounds__(256) alphabeta_kernel(const float* __restrict__ X)
{
    __shared__ float reda[8], redb[8];
    const int l = blockIdx.x;
    float sa = 0.0f, sb = 0.0f;
    for (int e = threadIdx.x; e < EDIM; e += 256) {
        float x = X[(size_t)l * EDIM + e];
        sa += x * g_w1[e];
        sb += x * g_w2[e];
    }
#pragma unroll
    for (int m = 16; m >= 1; m >>= 1) {
        sa += __shfl_xor_sync(0xffffffffu, sa, m);
        sb += __shfl_xor_sync(0xffffffffu, sb, m);
    }
    if ((threadIdx.x & 31) == 0) { reda[threadIdx.x >> 5] = sa; redb[threadIdx.x >> 5] = sb; }
    __syncthreads();
    if (threadIdx.x == 0) {
        float ta = 0.0f, tb = 0.0f;
#pragma unroll
        for (int i = 0; i < 8; i++) { ta += reda[i]; tb += redb[i]; }
        g_alpha[l] = ta;
        g_beta[l]  = tb;
    }
}

// ---------------------------------------------------------------------------
// mgemm: Mt[e'][e] = sum_h WkT16[e',h]*WqT16[e,h] (fp16 in, f32 acc, fp16 out)
// grid (8, 8)
// ---------------------------------------------------------------------------
__global__ void __launch_bounds__(256, 2) mgemm_kernel()
{
    extern __shared__ char dynsm[];
    const int m0 = blockIdx.y * 128;   // e'
    const int n0 = blockIdx.x * 128;   // e

    float acc[4][4][4];
#pragma unroll
    for (int a = 0; a < 4; a++)
#pragma unroll
        for (int b = 0; b < 4; b++)
#pragma unroll
            for (int cc = 0; cc < 4; cc++) acc[a][b][cc] = 0.0f;

    run_tile_h32(g_WkT16, g_WqT16, m0, n0, HDIM, dynsm, acc);

    const int tid = threadIdx.x;
    const int wid = tid >> 5, lane = tid & 31;
    const int wm = wid >> 2, wn = wid & 3;

#pragma unroll
    for (int mi = 0; mi < 4; mi++) {
        const int r0 = m0 + wm * 64 + mi * 16 + (lane >> 2);
#pragma unroll
        for (int ni = 0; ni < 4; ni++) {
            const int gc = n0 + wn * 32 + ni * 8 + 2 * (lane & 3);
#pragma unroll
            for (int hh = 0; hh < 2; hh++) {
                const int rr = r0 + hh * 8;
                *(__half2*)(g_M16 + (size_t)rr * EDIM + gc) =
                    __floats2half2_rn(acc[mi][ni][2 * hh], acc[mi][ni][2 * hh + 1]);
            }
        }
    }
}

// ---------------------------------------------------------------------------
// GEMM1: z=0: Qk = X16*M16^T (writes Qkf fp32 + Qk16 fp16)
//        z=1: V = X16*Wv16^T + bv (fp32 out)
// grid (8, 128, 2)
// ---------------------------------------------------------------------------
__global__ void __launch_bounds__(256, 2) gemm1_kernel(const float* __restrict__ bv)
{
    extern __shared__ char dynsm[];
    const int z  = blockIdx.z;
    const int m0 = blockIdx.y * 128;
    const int n0 = blockIdx.x * 128;

    float acc[4][4][4];
#pragma unroll
    for (int a = 0; a < 4; a++)
#pragma unroll
        for (int b = 0; b < 4; b++)
#pragma unroll
            for (int cc = 0; cc < 4; cc++) acc[a][b][cc] = 0.0f;

    run_tile_h32(g_X16, z ? g_Wv16 : g_M16, m0, n0, EDIM, dynsm, acc);

    const int tid = threadIdx.x;
    const int wid = tid >> 5, lane = tid & 31;
    const int wm = wid >> 2, wn = wid & 3;

#pragma unroll
    for (int mi = 0; mi < 4; mi++) {
        const int r0 = m0 + wm * 64 + mi * 16 + (lane >> 2);
#pragma unroll
        for (int ni = 0; ni < 4; ni++) {
            const int gc = n0 + wn * 32 + ni * 8 + 2 * (lane & 3);
            if (z == 1) {
                const float b0 = __ldg(&bv[gc]), b1 = __ldg(&bv[gc + 1]);
                *(float2*)(g_V + (size_t)r0 * HDIM + gc) =
                    make_float2(acc[mi][ni][0] + b0, acc[mi][ni][1] + b1);
                *(float2*)(g_V + (size_t)(r0 + 8) * HDIM + gc) =
                    make_float2(acc[mi][ni][2] + b0, acc[mi][ni][3] + b1);
            } else {
#pragma unroll
                for (int hh = 0; hh < 2; hh++) {
                    const int rr = r0 + hh * 8;
                    const float v0 = acc[mi][ni][2 * hh], v1 = acc[mi][ni][2 * hh + 1];
                    *(float2*)(g_Qkf + (size_t)rr * EDIM + gc) = make_float2(v0, v1);
                    *(__half2*)(g_Qk16 + (size_t)rr * EDIM + gc) = __floats2half2_rn(v0, v1);
                }
            }
        }
    }
}

// ---------------------------------------------------------------------------
// Diagonal: D[l] = Qkf[l] . X[l] (fp32); g_diag[l] = exp((D+a+b+c)*sc)
// ---------------------------------------------------------------------------
__global__ void __launch_bounds__(256) diagdot_kernel(const float* __restrict__ X)
{
    __shared__ float red[8];
    const int l = blockIdx.x;
    const float4* q = (const float4*)(g_Qkf + (size_t)l * EDIM);
    const float4* x = (const float4*)(X + (size_t)l * EDIM);
    float s = 0.0f;
    for (int i = threadIdx.x; i < EDIM / 4; i += 256) {
        float4 a = q[i], b = x[i];
        s += a.x * b.x + a.y * b.y + a.z * b.z + a.w * b.w;
    }
#pragma unroll
    for (int m = 16; m >= 1; m >>= 1) s += __shfl_xor_sync(0xffffffffu, s, m);
    if ((threadIdx.x & 31) == 0) red[threadIdx.x >> 5] = s;
    __syncthreads();
    if (threadIdx.x == 0) {
        float t = 0.0f;
#pragma unroll
        for (int i = 0; i < 8; i++) t += red[i];
        const float sc = 0.015625f;
        g_diag[l] = __expf((t + g_alpha[l] + g_beta[l] + g_c) * sc);
    }
}

// ---------------------------------------------------------------------------
// GEMM2: all tiles. S = Qk16 * X16^T (fp16 in, fp16 acc); exp + colsum.
// grid (32, 32, NB)
// ---------------------------------------------------------------------------
__global__ void __launch_bounds__(256, 2) gemm2_kernel()
{
    extern __shared__ char dynsm[];
    __shared__ float sred[128];

    const int bz = blockIdx.z;
    const int m0 = blockIdx.y * 128;
    const int n0 = blockIdx.x * 128;
    const int tid = threadIdx.x;
    const size_t bo = (size_t)bz * LSEQ * EDIM;

    if (tid < 128) sred[tid] = 0.0f;

    uint32_t acch[4][4][2];
#pragma unroll
    for (int a = 0; a < 4; a++)
#pragma unroll
        for (int b = 0; b < 4; b++) { acch[a][b][0] = 0; acch[a][b][1] = 0; }

    run_tile_h(g_Qk16 + bo, g_X16 + bo, m0, n0, EDIM, dynsm, acch);

    const int wid = tid >> 5, lane = tid & 31;
    const int wm = wid >> 2, wn = wid & 3;
    const float sc = 0.015625f;
    const float cc = g_c;

    float2 csum[4];
#pragma unroll
    for (int ni = 0; ni < 4; ni++) csum[ni] = make_float2(0.0f, 0.0f);

#pragma unroll
    for (int mi = 0; mi < 4; mi++) {
        const int lr = wm * 64 + mi * 16 + (lane >> 2);
        const float a0 = g_alpha[(size_t)bz * LSEQ + m0 + lr];
        const float a1 = g_alpha[(size_t)bz * LSEQ + m0 + lr + 8];
#pragma unroll
        for (int ni = 0; ni < 4; ni++) {
            const int lc = wn * 32 + ni * 8 + 2 * (lane & 3);
            const float b0 = g_beta[(size_t)bz * LSEQ + n0 + lc];
            const float b1 = g_beta[(size_t)bz * LSEQ + n0 + lc + 1];
            const __half2 p0 = *reinterpret_cast<__half2*>(&acch[mi][ni][0]);
            const __half2 p1 = *reinterpret_cast<__half2*>(&acch[mi][ni][1]);
            csum[ni].x += __expf((__half2float(p0.x) + a0 + b0 + cc) * sc)
                        + __expf((__half2float(p1.x) + a1 + b0 + cc) * sc);
            csum[ni].y += __expf((__half2float(p0.y) + a0 + b1 + cc) * sc)
                        + __expf((__half2float(p1.y) + a1 + b1 + cc) * sc);
        }
    }

    __syncthreads();   // sred init visible

#pragma unroll
    for (int ni = 0; ni < 4; ni++) {
#pragma unroll
        for (int m = 4; m <= 16; m <<= 1) {
            csum[ni].x += __shfl_xor_sync(0xffffffffu, csum[ni].x, m);
            csum[ni].y += __shfl_xor_sync(0xffffffffu, csum[ni].y, m);
        }
        if (lane < 4) {
            atomicAdd(&sred[wn * 32 + ni * 8 + 2 * lane],     csum[ni].x);
            atomicAdd(&sred[wn * 32 + ni * 8 + 2 * lane + 1], csum[ni].y);
        }
    }

    __syncthreads();
    if (tid < 128)
        atomicAdd(&g_colsum[(size_t)bz * LSEQ + n0 + tid], sred[tid]);
}

// ---------------------------------------------------------------------------
__global__ void __launch_bounds__(256) finalize_kernel(float* __restrict__ out)
{
    const int row = blockIdx.x;
    const float scale = g_diag[row] / g_colsum[row];
    const float4* v = (const float4*)(g_V + (size_t)row * HDIM);
    float4* o = (float4*)(out + (size_t)row * HDIM);
    float4 x = v[threadIdx.x];
    x.x *= scale; x.y *= scale; x.z *= scale; x.w *= scale;
    o[threadIdx.x] = x;
}

__global__ void zero_kernel()
{
    const int i = blockIdx.x * 256 + threadIdx.x;
    if (i < ML) g_colsum[i] = 0.0f;
}

// ---------------------------------------------------------------------------
extern "C" void kernel_launch(void* const* d_in, const int* in_sizes, int n_in,
                              void* d_out, int out_size)
{
    (void)in_sizes; (void)n_in; (void)out_size;
    const float* X  = (const float*)d_in[0];
    const float* Wq = (const float*)d_in[1];
    const float* bq = (const float*)d_in[2];
    const float* Wk = (const float*)d_in[3];
    const float* bk = (const float*)d_in[4];
    const float* Wv = (const float*)d_in[5];
    const float* bv = (const float*)d_in[6];
    float* out = (float*)d_out;

    // Idempotent host-side attribute setup (capture-safe, not stream ops).
    cudaFuncSetAttribute(mgemm_kernel,  cudaFuncAttributeMaxDynamicSharedMemorySize, DYNSMEM);
    cudaFuncSetAttribute(gemm1_kernel,  cudaFuncAttributeMaxDynamicSharedMemorySize, DYNSMEM);
    cudaFuncSetAttribute(gemm2_kernel,  cudaFuncAttributeMaxDynamicSharedMemorySize, DYNSMEM);
    cudaFuncSetAttribute(mgemm_kernel,  cudaFuncAttributePreferredSharedMemoryCarveout, 100);
    cudaFuncSetAttribute(gemm1_kernel,  cudaFuncAttributePreferredSharedMemoryCarveout, 100);
    cudaFuncSetAttribute(gemm2_kernel,  cudaFuncAttributePreferredSharedMemoryCarveout, 100);

    zero_kernel<<<(ML + 255) / 256, 256>>>();

    convx_kernel<<<(ML * EDIM / 4) / 256, 256>>>(X);
    convv_kernel<<<(HDIM * EDIM / 4) / 256, 256>>>(Wv);

    dim3 gt(EDIM / 32, HDIM / 32, 2);
    transw_kernel<<<gt, 256>>>(Wq, Wk);

    dim3 gb(EDIM, 2);
    biasw_kernel<<<gb, 256>>>(bq, bk);
    cscalar_kernel<<<1, 256>>>(bq, bk);

    dim3 gm(EDIM / 128, EDIM / 128);
    mgemm_kernel<<<gm, 256, DYNSMEM>>>();

    alphabeta_kernel<<<ML, 256>>>(X);

    dim3 g1(EDIM / 128, ML / 128, 2);
    gemm1_kernel<<<g1, 256, DYNSMEM>>>(bv);

    diagdot_kernel<<<ML, 256>>>(X);

    dim3 g2(LSEQ / 128, LSEQ / 128, NB);
    gemm2_kernel<<<g2, 256, DYNSMEM>>>();

    finalize_kernel<<<ML, 256>>>(out);
}